// round 2
// baseline (speedup 1.0000x reference)
#include <cuda_runtime.h>
#include <math.h>

#define NNODE 50000
#define NEDGE 800000
#define EPAD  (NEDGE + NNODE)   // edges + self loops
#define FDIM  256
#define NHEAD 4
#define CDIM  64
#define OUTD  64

// ---------------- scratch (static device memory; no allocs allowed) --------
__device__ float g_t[NNODE * FDIM];    // GEMM output (pre-aggregation feats), reused per layer
__device__ float g_h1[NNODE * FDIM];   // layer-1 output (post ELU)
__device__ float g_h2[NNODE * FDIM];   // layer-2 output (post ELU)
__device__ float g_als[NNODE * NHEAD];
__device__ float g_ald[NNODE * NHEAD];
__device__ int   g_deg[NNODE];
__device__ int   g_rowptr[NNODE + 1];
__device__ int   g_cursor[NNODE];
__device__ int   g_srcs[EPAD];

__device__ __forceinline__ int clampi(int v, int lo, int hi) {
    return v < lo ? lo : (v > hi ? hi : v);
}

// ---------------- CSR construction ----------------------------------------
__global__ void k_init_deg(int* deg) {
    int i = blockIdx.x * blockDim.x + threadIdx.x;
    if (i < NNODE) deg[i] = 1;   // self loop
}

// edge_index is int32 (JAX default: x64 disabled, int64 request -> int32)
__global__ void k_count_deg(const int* __restrict__ ei, int* deg) {
    int e = blockIdx.x * blockDim.x + threadIdx.x;
    if (e < NEDGE) {
        int d = clampi(ei[NEDGE + e], 0, NNODE - 1);
        atomicAdd(&deg[d], 1);
    }
}

// single-block exclusive scan (chunked Hillis-Steele), writes rowptr + cursor
__global__ void k_scan(const int* __restrict__ deg, int* rowptr, int* cursor) {
    __shared__ int sm[1024];
    int tid = threadIdx.x;
    int carry = 0;
    for (int base = 0; base < NNODE; base += 1024) {
        int i = base + tid;
        int v = (i < NNODE) ? deg[i] : 0;
        sm[tid] = v;
        __syncthreads();
        for (int off = 1; off < 1024; off <<= 1) {
            int t = 0;
            if (tid >= off) t = sm[tid - off];
            __syncthreads();
            sm[tid] += t;
            __syncthreads();
        }
        int excl = carry + sm[tid] - v;
        if (i < NNODE) { rowptr[i] = excl; cursor[i] = excl; }
        carry += sm[1023];
        __syncthreads();
    }
    if (tid == 0) rowptr[NNODE] = carry;
}

__global__ void k_scatter(const int* __restrict__ ei, int* cursor, int* srcs) {
    int e = blockIdx.x * blockDim.x + threadIdx.x;
    if (e < NEDGE) {
        int s = clampi(ei[e], 0, NNODE - 1);
        int d = clampi(ei[NEDGE + e], 0, NNODE - 1);
        int pos = atomicAdd(&cursor[d], 1);
        if (pos >= 0 && pos < EPAD) srcs[pos] = s;
    } else if (e < EPAD) {
        int i = e - NEDGE;
        int pos = atomicAdd(&cursor[i], 1);
        if (pos >= 0 && pos < EPAD) srcs[pos] = i;
    }
}

// ---------------- SGEMM: C[M,N] = A[M,K] @ B[K,N] (+bias) ------------------
template<int BM, int BN, int BK, int TM, int TN>
__global__ void k_sgemm(const float* __restrict__ A, const float* __restrict__ B,
                        const float* __restrict__ bias, float* __restrict__ C,
                        int M, int N, int K) {
    constexpr int THREADS = (BM / TM) * (BN / TN);
    __shared__ float As[BK][BM];
    __shared__ float Bs[BK][BN];
    int tid  = threadIdx.x;
    int brow = blockIdx.x * BM;
    int bcol = blockIdx.y * BN;
    int tcol = (tid % (BN / TN)) * TN;
    int trow = (tid / (BN / TN)) * TM;

    float acc[TM][TN];
#pragma unroll
    for (int i = 0; i < TM; i++)
#pragma unroll
        for (int j = 0; j < TN; j++) acc[i][j] = 0.f;

    for (int k0 = 0; k0 < K; k0 += BK) {
        // load A tile (BM x BK) transposed into As[BK][BM]
        for (int q = tid; q < (BM * BK) / 4; q += THREADS) {
            int arow = q / (BK / 4);
            int a4   = (q % (BK / 4)) * 4;
            float4 v = make_float4(0.f, 0.f, 0.f, 0.f);
            int gr = brow + arow;
            if (gr < M) v = *reinterpret_cast<const float4*>(&A[(size_t)gr * K + k0 + a4]);
            As[a4 + 0][arow] = v.x;
            As[a4 + 1][arow] = v.y;
            As[a4 + 2][arow] = v.z;
            As[a4 + 3][arow] = v.w;
        }
        // load B tile (BK x BN)
        for (int q = tid; q < (BK * BN) / 4; q += THREADS) {
            int br = q / (BN / 4);
            int b4 = (q % (BN / 4)) * 4;
            *reinterpret_cast<float4*>(&Bs[br][b4]) =
                *reinterpret_cast<const float4*>(&B[(size_t)(k0 + br) * N + bcol + b4]);
        }
        __syncthreads();
#pragma unroll
        for (int kk = 0; kk < BK; kk++) {
            float ar[TM], brv[TN];
#pragma unroll
            for (int i = 0; i < TM; i++) ar[i] = As[kk][trow + i];
#pragma unroll
            for (int j = 0; j < TN; j++) brv[j] = Bs[kk][tcol + j];
#pragma unroll
            for (int i = 0; i < TM; i++)
#pragma unroll
                for (int j = 0; j < TN; j++) acc[i][j] += ar[i] * brv[j];
        }
        __syncthreads();
    }

#pragma unroll
    for (int i = 0; i < TM; i++) {
        int gr = brow + trow + i;
        if (gr < M) {
#pragma unroll
            for (int j = 0; j < TN; j++) {
                float o = acc[i][j];
                if (bias) o += bias[bcol + tcol + j];
                C[(size_t)gr * N + bcol + tcol + j] = o;
            }
        }
    }
}

// ---------------- attention logits -----------------------------------------
// al_s[n,h] = sum_c t[n,h*64+c]*a_src[h,c];  al_d likewise. block=128 (1 warp/head)
__global__ void k_attn_logits(const float* __restrict__ t,
                              const float* __restrict__ a_src,
                              const float* __restrict__ a_dst,
                              float* __restrict__ als, float* __restrict__ ald) {
    int n    = blockIdx.x;
    int w    = threadIdx.x >> 5;   // head
    int lane = threadIdx.x & 31;
    float v0 = t[(size_t)n * FDIM + w * 64 + lane];
    float v1 = t[(size_t)n * FDIM + w * 64 + 32 + lane];
    float ps = v0 * a_src[w * 64 + lane] + v1 * a_src[w * 64 + 32 + lane];
    float pd = v0 * a_dst[w * 64 + lane] + v1 * a_dst[w * 64 + 32 + lane];
#pragma unroll
    for (int off = 16; off; off >>= 1) {
        ps += __shfl_xor_sync(0xffffffffu, ps, off);
        pd += __shfl_xor_sync(0xffffffffu, pd, off);
    }
    if (lane == 0) { als[n * NHEAD + w] = ps; ald[n * NHEAD + w] = pd; }
}

// ---------------- per-dst-node softmax + aggregation ------------------------
// block = 256 threads = 256 output channels; one block per node.
__global__ void k_gat_aggregate(const float* __restrict__ hsrc,
                                const int* __restrict__ rowptr,
                                const int* __restrict__ srcs,
                                const float* __restrict__ als,
                                const float* __restrict__ ald,
                                const float* __restrict__ bias,
                                float* __restrict__ out) {
    int n = blockIdx.x;
    int t = threadIdx.x;
    int slot = t >> 2;       // 0..63
    int head = t & 3;        // role for softmax math
    int head2 = t >> 6;      // channel-owner head (c = t)

    int p0  = rowptr[n];
    int deg = rowptr[n + 1] - p0;

    __shared__ float red[NHEAD][64];
    __shared__ float sw[64 * NHEAD];
    __shared__ int   ssrc[64];
    __shared__ float smax[NHEAD], sden[NHEAD];

    float aldv = ald[n * NHEAD + head];

    // pass 1: per-head max of leaky_relu(al_s[src]+al_d[n])
    float m = -1e30f;
    for (int j = slot; j < deg; j += 64) {
        int s = srcs[p0 + j];
        float e = als[s * NHEAD + head] + aldv;
        e = (e > 0.f) ? e : 0.2f * e;
        m = fmaxf(m, e);
    }
    red[head][slot] = m;
    __syncthreads();
    for (int off = 32; off >= 1; off >>= 1) {
        if (slot < off) red[head][slot] = fmaxf(red[head][slot], red[head][slot + off]);
        __syncthreads();
    }
    if (t < NHEAD) smax[t] = red[t][0];
    __syncthreads();
    float mx = smax[head];

    // pass 2: denominator
    float dsum = 0.f;
    for (int j = slot; j < deg; j += 64) {
        int s = srcs[p0 + j];
        float e = als[s * NHEAD + head] + aldv;
        e = (e > 0.f) ? e : 0.2f * e;
        dsum += __expf(e - mx);
    }
    red[head][slot] = dsum;
    __syncthreads();
    for (int off = 32; off >= 1; off >>= 1) {
        if (slot < off) red[head][slot] += red[head][slot + off];
        __syncthreads();
    }
    if (t < NHEAD) sden[t] = red[t][0];
    __syncthreads();

    float invden = 1.f / sden[head];

    // pass 3: chunked weighted aggregation
    float acc = 0.f;
    for (int base = 0; base < deg; base += 64) {
        int j = base + slot;
        if (j < deg) {
            int s = srcs[p0 + j];
            if (head == 0) ssrc[slot] = s;
            float e = als[s * NHEAD + head] + aldv;
            e = (e > 0.f) ? e : 0.2f * e;
            sw[slot * NHEAD + head] = __expf(e - mx) * invden;
        }
        __syncthreads();
        int lim = min(64, deg - base);
#pragma unroll 4
        for (int j2 = 0; j2 < lim; j2++) {
            acc += sw[j2 * NHEAD + head2] * hsrc[(size_t)ssrc[j2] * FDIM + t];
        }
        __syncthreads();
    }

    float o = acc + bias[t];
    o = (o > 0.f) ? o : expm1f(o);   // ELU
    out[(size_t)n * FDIM + t] = o;
}

// ---------------- launch ----------------------------------------------------
extern "C" void kernel_launch(void* const* d_in, const int* in_sizes, int n_in,
                              void* d_out, int out_size) {
    const float* x     = (const float*)d_in[0];
    const int*   ei    = (const int*)d_in[1];   // int32! (JAX default x64-disabled)
    // d_in[2] = batch (unused)
    const float* W1    = (const float*)d_in[3];
    const float* asrc1 = (const float*)d_in[4];
    const float* adst1 = (const float*)d_in[5];
    const float* b1    = (const float*)d_in[6];
    const float* W2    = (const float*)d_in[7];
    const float* asrc2 = (const float*)d_in[8];
    const float* adst2 = (const float*)d_in[9];
    const float* b2    = (const float*)d_in[10];
    const float* fcW   = (const float*)d_in[11];
    const float* fcb   = (const float*)d_in[12];
    float* out = (float*)d_out;

    float *t, *h1, *h2, *als, *ald;
    int *deg, *rowptr, *cursor, *srcs;
    cudaGetSymbolAddress((void**)&t, g_t);
    cudaGetSymbolAddress((void**)&h1, g_h1);
    cudaGetSymbolAddress((void**)&h2, g_h2);
    cudaGetSymbolAddress((void**)&als, g_als);
    cudaGetSymbolAddress((void**)&ald, g_ald);
    cudaGetSymbolAddress((void**)&deg, g_deg);
    cudaGetSymbolAddress((void**)&rowptr, g_rowptr);
    cudaGetSymbolAddress((void**)&cursor, g_cursor);
    cudaGetSymbolAddress((void**)&srcs, g_srcs);

    // CSR by dst
    k_init_deg<<<(NNODE + 255) / 256, 256>>>(deg);
    k_count_deg<<<(NEDGE + 255) / 256, 256>>>(ei, deg);
    k_scan<<<1, 1024>>>(deg, rowptr, cursor);
    k_scatter<<<(EPAD + 255) / 256, 256>>>(ei, cursor, srcs);

    dim3 g1((NNODE + 127) / 128, FDIM / 128);
    dim3 gfc((NNODE + 127) / 128, OUTD / 64);

    // layer 1
    k_sgemm<128, 128, 8, 8, 8><<<g1, 256>>>(x, W1, nullptr, t, NNODE, FDIM, FDIM);
    k_attn_logits<<<NNODE, 128>>>(t, asrc1, adst1, als, ald);
    k_gat_aggregate<<<NNODE, 256>>>(t, rowptr, srcs, als, ald, b1, h1);

    // layer 2
    k_sgemm<128, 128, 8, 8, 8><<<g1, 256>>>(h1, W2, nullptr, t, NNODE, FDIM, FDIM);
    k_attn_logits<<<NNODE, 128>>>(t, asrc2, adst2, als, ald);
    k_gat_aggregate<<<NNODE, 256>>>(t, rowptr, srcs, als, ald, b2, h2);

    // fc head
    k_sgemm<128, 64, 8, 8, 4><<<gfc, 256>>>(h2, fcW, fcb, out, NNODE, OUTD, FDIM);
}

// round 3
// speedup vs baseline: 1.0908x; 1.0908x over previous
#include <cuda_runtime.h>
#include <math.h>

#define NNODE 50000
#define NEDGE 800000
#define EPAD  (NEDGE + NNODE)   // edges + self loops
#define FDIM  256
#define NHEAD 4
#define CDIM  64
#define OUTD  64

// ---------------- scratch (static device memory; no allocs allowed) --------
__device__ float g_t[NNODE * FDIM];    // GEMM output (pre-aggregation feats)
__device__ float g_h1[NNODE * FDIM];   // layer-1 output (post ELU)
__device__ float g_h2[NNODE * FDIM];   // layer-2 output (post ELU)
__device__ float g_als[NNODE * NHEAD];
__device__ float g_ald[NNODE * NHEAD];
__device__ int   g_deg[NNODE];
__device__ int   g_rowptr[NNODE + 1];
__device__ int   g_cursor[NNODE];
__device__ int   g_srcs[EPAD];

__device__ __forceinline__ int clampi(int v, int lo, int hi) {
    return v < lo ? lo : (v > hi ? hi : v);
}

// packed fp32x2 FMA (full-rate fp32 on B300; 3-reg FFMA is half-rate)
__device__ __forceinline__ unsigned long long ffma2(unsigned long long a,
                                                    unsigned long long b,
                                                    unsigned long long c) {
    unsigned long long d;
    asm("fma.rn.f32x2 %0, %1, %2, %3;" : "=l"(d) : "l"(a), "l"(b), "l"(c));
    return d;
}
__device__ __forceinline__ unsigned long long dup2(float x) {
    unsigned long long d;
    asm("mov.b64 %0, {%1, %1};" : "=l"(d) : "f"(x));
    return d;
}
__device__ __forceinline__ void unpack2(unsigned long long p, float& lo, float& hi) {
    asm("mov.b64 {%0, %1}, %2;" : "=f"(lo), "=f"(hi) : "l"(p));
}

// ---------------- CSR construction ----------------------------------------
__global__ void k_init_deg(int* deg) {
    int i = blockIdx.x * blockDim.x + threadIdx.x;
    if (i < NNODE) deg[i] = 1;   // self loop
}

// edge_index is int32 (JAX default: x64 disabled -> int64 request yields int32)
__global__ void k_count_deg(const int* __restrict__ ei, int* deg) {
    int e = blockIdx.x * blockDim.x + threadIdx.x;
    if (e < NEDGE) {
        int d = clampi(ei[NEDGE + e], 0, NNODE - 1);
        atomicAdd(&deg[d], 1);
    }
}

__global__ void k_scan(const int* __restrict__ deg, int* rowptr, int* cursor) {
    __shared__ int sm[1024];
    int tid = threadIdx.x;
    int carry = 0;
    for (int base = 0; base < NNODE; base += 1024) {
        int i = base + tid;
        int v = (i < NNODE) ? deg[i] : 0;
        sm[tid] = v;
        __syncthreads();
        for (int off = 1; off < 1024; off <<= 1) {
            int t = 0;
            if (tid >= off) t = sm[tid - off];
            __syncthreads();
            sm[tid] += t;
            __syncthreads();
        }
        int excl = carry + sm[tid] - v;
        if (i < NNODE) { rowptr[i] = excl; cursor[i] = excl; }
        carry += sm[1023];
        __syncthreads();
    }
    if (tid == 0) rowptr[NNODE] = carry;
}

__global__ void k_scatter(const int* __restrict__ ei, int* cursor, int* srcs) {
    int e = blockIdx.x * blockDim.x + threadIdx.x;
    if (e < NEDGE) {
        int s = clampi(ei[e], 0, NNODE - 1);
        int d = clampi(ei[NEDGE + e], 0, NNODE - 1);
        int pos = atomicAdd(&cursor[d], 1);
        if (pos >= 0 && pos < EPAD) srcs[pos] = s;
    } else if (e < EPAD) {
        int i = e - NEDGE;
        int pos = atomicAdd(&cursor[i], 1);
        if (pos >= 0 && pos < EPAD) srcs[pos] = i;
    }
}

// ---------------- SGEMM v2: FFMA2 + double buffering ------------------------
// C[M,N] = A[M,K] @ B[K,N] (+bias). Row-pair accumulators in packed f32x2.
template<int BM, int BN, int BK, int TM, int TN>
__global__ void __launch_bounds__((BM / TM) * (BN / TN), 2)
k_sgemm2(const float* __restrict__ A, const float* __restrict__ B,
         const float* __restrict__ bias, float* __restrict__ C,
         int M, int N, int K) {
    constexpr int THREADS = (BM / TM) * (BN / TN);
    constexpr int A_F4 = BM * BK / 4;   // float4 slots per A tile
    constexpr int B_F4 = BK * BN / 4;
    constexpr int A_LD = A_F4 / THREADS;
    constexpr int B_LD = B_F4 / THREADS;

    __shared__ float As[2][BK][BM];   // transposed: As[k][row]
    __shared__ float Bs[2][BK][BN];

    int tid  = threadIdx.x;
    int brow = blockIdx.x * BM;
    int bcol = blockIdx.y * BN;
    int tcol = (tid % (BN / TN)) * TN;
    int trow = (tid / (BN / TN)) * TM;

    unsigned long long acc2[TM / 2][TN];
#pragma unroll
    for (int i = 0; i < TM / 2; i++)
#pragma unroll
        for (int j = 0; j < TN; j++) acc2[i][j] = 0ull;

    float4 aS[A_LD], bS[B_LD];

    auto load_regs = [&](int k0) {
#pragma unroll
        for (int u = 0; u < A_LD; u++) {
            int q    = tid + u * THREADS;
            int arow = q / (BK / 4);
            int a4   = (q % (BK / 4)) * 4;
            int gr   = brow + arow;
            aS[u] = make_float4(0.f, 0.f, 0.f, 0.f);
            if (gr < M) aS[u] = *reinterpret_cast<const float4*>(&A[(size_t)gr * K + k0 + a4]);
        }
#pragma unroll
        for (int u = 0; u < B_LD; u++) {
            int q  = tid + u * THREADS;
            int br = q / (BN / 4);
            int b4 = (q % (BN / 4)) * 4;
            bS[u] = *reinterpret_cast<const float4*>(&B[(size_t)(k0 + br) * N + bcol + b4]);
        }
    };
    auto store_smem = [&](int buf) {
#pragma unroll
        for (int u = 0; u < A_LD; u++) {
            int q    = tid + u * THREADS;
            int arow = q / (BK / 4);
            int a4   = (q % (BK / 4)) * 4;
            As[buf][a4 + 0][arow] = aS[u].x;
            As[buf][a4 + 1][arow] = aS[u].y;
            As[buf][a4 + 2][arow] = aS[u].z;
            As[buf][a4 + 3][arow] = aS[u].w;
        }
#pragma unroll
        for (int u = 0; u < B_LD; u++) {
            int q  = tid + u * THREADS;
            int br = q / (BN / 4);
            int b4 = (q % (BN / 4)) * 4;
            *reinterpret_cast<float4*>(&Bs[buf][br][b4]) = bS[u];
        }
    };

    const int NT = K / BK;
    load_regs(0);
    store_smem(0);
    __syncthreads();

    int cur = 0;
    for (int t = 0; t < NT; t++) {
        if (t + 1 < NT) load_regs((t + 1) * BK);

        const unsigned long long* As64 =
            reinterpret_cast<const unsigned long long*>(&As[cur][0][0]);
#pragma unroll
        for (int kk = 0; kk < BK; kk++) {
            unsigned long long ap[TM / 2];
#pragma unroll
            for (int i = 0; i < TM / 2; i++)
                ap[i] = As64[(kk * BM + trow) / 2 + i];
            unsigned long long bd[TN];
#pragma unroll
            for (int j = 0; j < TN; j++)
                bd[j] = dup2(Bs[cur][kk][tcol + j]);
#pragma unroll
            for (int i = 0; i < TM / 2; i++)
#pragma unroll
                for (int j = 0; j < TN; j++)
                    acc2[i][j] = ffma2(ap[i], bd[j], acc2[i][j]);
        }

        if (t + 1 < NT) {
            store_smem(cur ^ 1);
            __syncthreads();
            cur ^= 1;
        }
    }

    // epilogue: unpack pairs, add bias, vectorized stores
#pragma unroll
    for (int i = 0; i < TM / 2; i++) {
        float lo[TN], hi[TN];
#pragma unroll
        for (int j = 0; j < TN; j++) unpack2(acc2[i][j], lo[j], hi[j]);
#pragma unroll
        for (int half = 0; half < 2; half++) {
            int gr = brow + trow + 2 * i + half;
            if (gr >= M) continue;
            float* rowv = half ? hi : lo;
#pragma unroll
            for (int j4 = 0; j4 < TN; j4 += 4) {
                float4 v;
                v.x = rowv[j4 + 0]; v.y = rowv[j4 + 1];
                v.z = rowv[j4 + 2]; v.w = rowv[j4 + 3];
                if (bias) {
                    v.x += bias[bcol + tcol + j4 + 0];
                    v.y += bias[bcol + tcol + j4 + 1];
                    v.z += bias[bcol + tcol + j4 + 2];
                    v.w += bias[bcol + tcol + j4 + 3];
                }
                *reinterpret_cast<float4*>(&C[(size_t)gr * N + bcol + tcol + j4]) = v;
            }
        }
    }
}

// ---------------- attention logits -----------------------------------------
__global__ void k_attn_logits(const float* __restrict__ t,
                              const float* __restrict__ a_src,
                              const float* __restrict__ a_dst,
                              float* __restrict__ als, float* __restrict__ ald) {
    int n    = blockIdx.x;
    int w    = threadIdx.x >> 5;   // head
    int lane = threadIdx.x & 31;
    float v0 = t[(size_t)n * FDIM + w * 64 + lane];
    float v1 = t[(size_t)n * FDIM + w * 64 + 32 + lane];
    float ps = v0 * a_src[w * 64 + lane] + v1 * a_src[w * 64 + 32 + lane];
    float pd = v0 * a_dst[w * 64 + lane] + v1 * a_dst[w * 64 + 32 + lane];
#pragma unroll
    for (int off = 16; off; off >>= 1) {
        ps += __shfl_xor_sync(0xffffffffu, ps, off);
        pd += __shfl_xor_sync(0xffffffffu, pd, off);
    }
    if (lane == 0) { als[n * NHEAD + w] = ps; ald[n * NHEAD + w] = pd; }
}

// ---------------- per-dst-node softmax + aggregation ------------------------
__global__ void k_gat_aggregate(const float* __restrict__ hsrc,
                                const int* __restrict__ rowptr,
                                const int* __restrict__ srcs,
                                const float* __restrict__ als,
                                const float* __restrict__ ald,
                                const float* __restrict__ bias,
                                float* __restrict__ out) {
    int n = blockIdx.x;
    int t = threadIdx.x;
    int slot = t >> 2;       // 0..63
    int head = t & 3;        // role for softmax math
    int head2 = t >> 6;      // channel-owner head (c = t)

    int p0  = rowptr[n];
    int deg = rowptr[n + 1] - p0;

    __shared__ float red[NHEAD][64];
    __shared__ float sw[64 * NHEAD];
    __shared__ int   ssrc[64];
    __shared__ float smax[NHEAD], sden[NHEAD];

    float aldv = ald[n * NHEAD + head];

    // pass 1: per-head max of leaky_relu(al_s[src]+al_d[n])
    float m = -1e30f;
    for (int j = slot; j < deg; j += 64) {
        int s = srcs[p0 + j];
        float e = als[s * NHEAD + head] + aldv;
        e = (e > 0.f) ? e : 0.2f * e;
        m = fmaxf(m, e);
    }
    red[head][slot] = m;
    __syncthreads();
    for (int off = 32; off >= 1; off >>= 1) {
        if (slot < off) red[head][slot] = fmaxf(red[head][slot], red[head][slot + off]);
        __syncthreads();
    }
    if (t < NHEAD) smax[t] = red[t][0];
    __syncthreads();
    float mx = smax[head];

    // pass 2: denominator
    float dsum = 0.f;
    for (int j = slot; j < deg; j += 64) {
        int s = srcs[p0 + j];
        float e = als[s * NHEAD + head] + aldv;
        e = (e > 0.f) ? e : 0.2f * e;
        dsum += __expf(e - mx);
    }
    red[head][slot] = dsum;
    __syncthreads();
    for (int off = 32; off >= 1; off >>= 1) {
        if (slot < off) red[head][slot] += red[head][slot + off];
        __syncthreads();
    }
    if (t < NHEAD) sden[t] = red[t][0];
    __syncthreads();

    float invden = 1.f / sden[head];

    // pass 3: chunked weighted aggregation
    float acc = 0.f;
    for (int base = 0; base < deg; base += 64) {
        int j = base + slot;
        if (j < deg) {
            int s = srcs[p0 + j];
            if (head == 0) ssrc[slot] = s;
            float e = als[s * NHEAD + head] + aldv;
            e = (e > 0.f) ? e : 0.2f * e;
            sw[slot * NHEAD + head] = __expf(e - mx) * invden;
        }
        __syncthreads();
        int lim = min(64, deg - base);
#pragma unroll 4
        for (int j2 = 0; j2 < lim; j2++) {
            acc += sw[j2 * NHEAD + head2] * hsrc[(size_t)ssrc[j2] * FDIM + t];
        }
        __syncthreads();
    }

    float o = acc + bias[t];
    o = (o > 0.f) ? o : expm1f(o);   // ELU
    out[(size_t)n * FDIM + t] = o;
}

// ---------------- launch ----------------------------------------------------
extern "C" void kernel_launch(void* const* d_in, const int* in_sizes, int n_in,
                              void* d_out, int out_size) {
    const float* x     = (const float*)d_in[0];
    const int*   ei    = (const int*)d_in[1];   // int32 (JAX x64 disabled)
    const float* W1    = (const float*)d_in[3];
    const float* asrc1 = (const float*)d_in[4];
    const float* adst1 = (const float*)d_in[5];
    const float* b1    = (const float*)d_in[6];
    const float* W2    = (const float*)d_in[7];
    const float* asrc2 = (const float*)d_in[8];
    const float* adst2 = (const float*)d_in[9];
    const float* b2    = (const float*)d_in[10];
    const float* fcW   = (const float*)d_in[11];
    const float* fcb   = (const float*)d_in[12];
    float* out = (float*)d_out;

    float *t, *h1, *h2, *als, *ald;
    int *deg, *rowptr, *cursor, *srcs;
    cudaGetSymbolAddress((void**)&t, g_t);
    cudaGetSymbolAddress((void**)&h1, g_h1);
    cudaGetSymbolAddress((void**)&h2, g_h2);
    cudaGetSymbolAddress((void**)&als, g_als);
    cudaGetSymbolAddress((void**)&ald, g_ald);
    cudaGetSymbolAddress((void**)&deg, g_deg);
    cudaGetSymbolAddress((void**)&rowptr, g_rowptr);
    cudaGetSymbolAddress((void**)&cursor, g_cursor);
    cudaGetSymbolAddress((void**)&srcs, g_srcs);

    // CSR by dst
    k_init_deg<<<(NNODE + 255) / 256, 256>>>(deg);
    k_count_deg<<<(NEDGE + 255) / 256, 256>>>(ei, deg);
    k_scan<<<1, 1024>>>(deg, rowptr, cursor);
    k_scatter<<<(EPAD + 255) / 256, 256>>>(ei, cursor, srcs);

    dim3 g1((NNODE + 127) / 128, FDIM / 128);
    dim3 gfc((NNODE + 127) / 128, OUTD / 64);

    // layer 1
    k_sgemm2<128, 128, 16, 8, 8><<<g1, 256>>>(x, W1, nullptr, t, NNODE, FDIM, FDIM);
    k_attn_logits<<<NNODE, 128>>>(t, asrc1, adst1, als, ald);
    k_gat_aggregate<<<NNODE, 256>>>(t, rowptr, srcs, als, ald, b1, h1);

    // layer 2
    k_sgemm2<128, 128, 16, 8, 8><<<g1, 256>>>(h1, W2, nullptr, t, NNODE, FDIM, FDIM);
    k_attn_logits<<<NNODE, 128>>>(t, asrc2, adst2, als, ald);
    k_gat_aggregate<<<NNODE, 256>>>(t, rowptr, srcs, als, ald, b2, h2);

    // fc head
    k_sgemm2<128, 64, 16, 8, 4><<<gfc, 256>>>(h2, fcW, fcb, out, NNODE, OUTD, FDIM);
}

// round 5
// speedup vs baseline: 1.3680x; 1.2541x over previous
#include <cuda_runtime.h>
#include <math.h>
#include <stdint.h>

#define NNODE 50000
#define NEDGE 800000
#define EPAD  (NEDGE + NNODE)
#define FDIM  256
#define NHEAD 4
#define OUTD  64

// ---------------- scratch ---------------------------------------------------
__device__ __align__(128) float g_t[NNODE * FDIM];
__device__ __align__(128) float g_h1[NNODE * FDIM];
__device__ __align__(128) float g_h2[NNODE * FDIM];
__device__ __align__(128) float g_wt1[FDIM * FDIM];   // W1^T [N][K]
__device__ __align__(128) float g_wt2[FDIM * FDIM];   // W2^T
__device__ __align__(128) float g_wtfc[OUTD * FDIM];  // fcW^T
__device__ float g_als[NNODE * NHEAD];
__device__ float g_ald[NNODE * NHEAD];
__device__ int   g_deg[NNODE];
__device__ int   g_rowptr[NNODE + 1];
__device__ int   g_cursor[NNODE];
__device__ int   g_srcs[EPAD];

__device__ __forceinline__ int clampi(int v, int lo, int hi) {
    return v < lo ? lo : (v > hi ? hi : v);
}

// pack two floats to bf16x2 word: lo -> bits[15:0], hi -> bits[31:16]
__device__ __forceinline__ uint32_t pack_bf16x2(float lo, float hi) {
    uint32_t d;
    asm("cvt.rn.bf16x2.f32 %0, %1, %2;" : "=r"(d) : "f"(hi), "f"(lo));
    return d;
}

__device__ __forceinline__ void mma_bf16(float* d, const uint32_t* a, const uint32_t* b) {
    asm volatile(
        "mma.sync.aligned.m16n8k16.row.col.f32.bf16.bf16.f32 "
        "{%0,%1,%2,%3}, {%4,%5,%6,%7}, {%8,%9}, {%0,%1,%2,%3};"
        : "+f"(d[0]), "+f"(d[1]), "+f"(d[2]), "+f"(d[3])
        : "r"(a[0]), "r"(a[1]), "r"(a[2]), "r"(a[3]), "r"(b[0]), "r"(b[1]));
}

// ---------------- CSR construction ------------------------------------------
__global__ void k_init_deg(int* deg) {
    int i = blockIdx.x * blockDim.x + threadIdx.x;
    if (i < NNODE) deg[i] = 1;
}
__global__ void k_count_deg(const int* __restrict__ ei, int* deg) {
    int e = blockIdx.x * blockDim.x + threadIdx.x;
    if (e < NEDGE) atomicAdd(&deg[clampi(ei[NEDGE + e], 0, NNODE - 1)], 1);
}
__global__ void k_scan(const int* __restrict__ deg, int* rowptr, int* cursor) {
    __shared__ int sm[1024];
    int tid = threadIdx.x;
    int carry = 0;
    for (int base = 0; base < NNODE; base += 1024) {
        int i = base + tid;
        int v = (i < NNODE) ? deg[i] : 0;
        sm[tid] = v;
        __syncthreads();
        for (int off = 1; off < 1024; off <<= 1) {
            int t = 0;
            if (tid >= off) t = sm[tid - off];
            __syncthreads();
            sm[tid] += t;
            __syncthreads();
        }
        int excl = carry + sm[tid] - v;
        if (i < NNODE) { rowptr[i] = excl; cursor[i] = excl; }
        carry += sm[1023];
        __syncthreads();
    }
    if (tid == 0) rowptr[NNODE] = carry;
}
__global__ void k_scatter(const int* __restrict__ ei, int* cursor, int* srcs) {
    int e = blockIdx.x * blockDim.x + threadIdx.x;
    if (e < NEDGE) {
        int s = clampi(ei[e], 0, NNODE - 1);
        int d = clampi(ei[NEDGE + e], 0, NNODE - 1);
        int pos = atomicAdd(&cursor[d], 1);
        if (pos >= 0 && pos < EPAD) srcs[pos] = s;
    } else if (e < EPAD) {
        int i = e - NEDGE;
        int pos = atomicAdd(&cursor[i], 1);
        if (pos >= 0 && pos < EPAD) srcs[pos] = i;
    }
}

// ---------------- weight transpose: WT[n][k] = W[k][n] ----------------------
__global__ void k_transpose(const float* __restrict__ W, float* __restrict__ WT,
                            int K, int N) {
    int i = blockIdx.x * blockDim.x + threadIdx.x;
    if (i < K * N) {
        int k = i / N, n = i % N;
        WT[n * K + k] = W[i];
    }
}

// ---------------- bf16-split tensor-core GEMM --------------------------------
// C[M, NOUT] = A[M,256] @ B (B given as BT[NOUT][256], K-major) (+bias).
// Block tile 128 x BN, 8 warps (4 m x 2 n), BK=32 (two k16 steps).
// 3-product split: D += Ahi*Bhi + Ahi*Blo + Alo*Bhi.
template<int BN, int NOUT>
__global__ void __launch_bounds__(256, 1)
k_gemm_mma(const float* __restrict__ A, const float* __restrict__ BT,
           const float* __restrict__ bias, float* __restrict__ C, int M) {
    constexpr int RS = 40;           // smem row stride in bf16 elems (conflict-free)
    constexpr int WN = BN / 2;       // warp n extent
    constexpr int NT = WN / 8;       // 8-col mma tiles per warp
    constexpr int A_F4 = 128 * 8 / 256;   // float4 loads per thread (A tile)
    constexpr int B_F4 = BN * 8 / 256;

    __shared__ __align__(16) uint16_t sAh[128 * RS];
    __shared__ __align__(16) uint16_t sAl[128 * RS];
    __shared__ __align__(16) uint16_t sBh[BN * RS];
    __shared__ __align__(16) uint16_t sBl[BN * RS];

    const int tid  = threadIdx.x;
    const int wid  = tid >> 5, lane = tid & 31;
    const int wm   = wid & 3, wn = wid >> 2;
    const int g    = lane >> 2, tq = lane & 3;
    const int brow = blockIdx.x * 128;
    const int bcol = blockIdx.y * BN;

    float acc[2][NT][4];
#pragma unroll
    for (int mt = 0; mt < 2; mt++)
#pragma unroll
        for (int nt = 0; nt < NT; nt++)
#pragma unroll
            for (int r = 0; r < 4; r++) acc[mt][nt][r] = 0.f;

    float4 aS[A_F4], bS[B_F4];

    auto load_regs = [&](int k0) {
#pragma unroll
        for (int u = 0; u < A_F4; u++) {
            int q = tid + u * 256;
            int row = q >> 3, f4 = q & 7;
            int gr = brow + row;
            aS[u] = make_float4(0.f, 0.f, 0.f, 0.f);
            if (gr < M) aS[u] = *reinterpret_cast<const float4*>(&A[(size_t)gr * 256 + k0 + f4 * 4]);
        }
#pragma unroll
        for (int u = 0; u < B_F4; u++) {
            int q = tid + u * 256;
            int row = q >> 3, f4 = q & 7;
            bS[u] = *reinterpret_cast<const float4*>(&BT[(size_t)(bcol + row) * 256 + k0 + f4 * 4]);
        }
    };

    auto split_store = [](uint16_t* hbase, uint16_t* lbase, int idx, float v0, float v1) {
        uint32_t hw = pack_bf16x2(v0, v1);
        float f0 = __uint_as_float(hw << 16);
        float f1 = __uint_as_float(hw & 0xffff0000u);
        uint32_t lw = pack_bf16x2(v0 - f0, v1 - f1);
        *reinterpret_cast<uint32_t*>(hbase + idx) = hw;
        *reinterpret_cast<uint32_t*>(lbase + idx) = lw;
    };

    auto store_smem = [&]() {
#pragma unroll
        for (int u = 0; u < A_F4; u++) {
            int q = tid + u * 256;
            int row = q >> 3, f4 = q & 7;
            int idx = row * RS + f4 * 4;
            split_store(sAh, sAl, idx,     aS[u].x, aS[u].y);
            split_store(sAh, sAl, idx + 2, aS[u].z, aS[u].w);
        }
#pragma unroll
        for (int u = 0; u < B_F4; u++) {
            int q = tid + u * 256;
            int row = q >> 3, f4 = q & 7;
            int idx = row * RS + f4 * 4;
            split_store(sBh, sBl, idx,     bS[u].x, bS[u].y);
            split_store(sBh, sBl, idx + 2, bS[u].z, bS[u].w);
        }
    };

    load_regs(0);
    store_smem();
    __syncthreads();

    for (int t = 0; t < 8; t++) {
        if (t + 1 < 8) load_regs((t + 1) * 32);

#pragma unroll
        for (int ks = 0; ks < 2; ks++) {
            const int kb = ks * 16;
            uint32_t ah[2][4], al[2][4];
#pragma unroll
            for (int mt = 0; mt < 2; mt++) {
                int r0 = (wm * 32 + mt * 16 + g) * RS;
                int r8 = r0 + 8 * RS;
                ah[mt][0] = *reinterpret_cast<const uint32_t*>(&sAh[r0 + kb + tq * 2]);
                ah[mt][1] = *reinterpret_cast<const uint32_t*>(&sAh[r8 + kb + tq * 2]);
                ah[mt][2] = *reinterpret_cast<const uint32_t*>(&sAh[r0 + kb + 8 + tq * 2]);
                ah[mt][3] = *reinterpret_cast<const uint32_t*>(&sAh[r8 + kb + 8 + tq * 2]);
                al[mt][0] = *reinterpret_cast<const uint32_t*>(&sAl[r0 + kb + tq * 2]);
                al[mt][1] = *reinterpret_cast<const uint32_t*>(&sAl[r8 + kb + tq * 2]);
                al[mt][2] = *reinterpret_cast<const uint32_t*>(&sAl[r0 + kb + 8 + tq * 2]);
                al[mt][3] = *reinterpret_cast<const uint32_t*>(&sAl[r8 + kb + 8 + tq * 2]);
            }
#pragma unroll
            for (int nt = 0; nt < NT; nt++) {
                int nr = (wn * WN + nt * 8 + g) * RS;
                uint32_t bh[2], bl[2];
                bh[0] = *reinterpret_cast<const uint32_t*>(&sBh[nr + kb + tq * 2]);
                bh[1] = *reinterpret_cast<const uint32_t*>(&sBh[nr + kb + 8 + tq * 2]);
                bl[0] = *reinterpret_cast<const uint32_t*>(&sBl[nr + kb + tq * 2]);
                bl[1] = *reinterpret_cast<const uint32_t*>(&sBl[nr + kb + 8 + tq * 2]);
#pragma unroll
                for (int mt = 0; mt < 2; mt++) {
                    mma_bf16(acc[mt][nt], ah[mt], bh);
                    mma_bf16(acc[mt][nt], ah[mt], bl);
                    mma_bf16(acc[mt][nt], al[mt], bh);
                }
            }
        }

        if (t + 1 < 8) {
            __syncthreads();
            store_smem();
            __syncthreads();
        }
    }

    // epilogue: fragment-direct float2 stores
#pragma unroll
    for (int mt = 0; mt < 2; mt++) {
        int r0 = brow + wm * 32 + mt * 16 + g;
        int r1 = r0 + 8;
#pragma unroll
        for (int nt = 0; nt < NT; nt++) {
            int col = bcol + wn * WN + nt * 8 + tq * 2;
            float b0 = 0.f, b1 = 0.f;
            if (bias) { b0 = bias[col]; b1 = bias[col + 1]; }
            if (r0 < M) {
                float2 v = make_float2(acc[mt][nt][0] + b0, acc[mt][nt][1] + b1);
                *reinterpret_cast<float2*>(&C[(size_t)r0 * NOUT + col]) = v;
            }
            if (r1 < M) {
                float2 v = make_float2(acc[mt][nt][2] + b0, acc[mt][nt][3] + b1);
                *reinterpret_cast<float2*>(&C[(size_t)r1 * NOUT + col]) = v;
            }
        }
    }
}

// ---------------- attention logits ------------------------------------------
__global__ void k_attn_logits(const float* __restrict__ t,
                              const float* __restrict__ a_src,
                              const float* __restrict__ a_dst,
                              float* __restrict__ als, float* __restrict__ ald) {
    int n    = blockIdx.x;
    int w    = threadIdx.x >> 5;
    int lane = threadIdx.x & 31;
    float v0 = t[(size_t)n * FDIM + w * 64 + lane];
    float v1 = t[(size_t)n * FDIM + w * 64 + 32 + lane];
    float ps = v0 * a_src[w * 64 + lane] + v1 * a_src[w * 64 + 32 + lane];
    float pd = v0 * a_dst[w * 64 + lane] + v1 * a_dst[w * 64 + 32 + lane];
#pragma unroll
    for (int off = 16; off; off >>= 1) {
        ps += __shfl_xor_sync(0xffffffffu, ps, off);
        pd += __shfl_xor_sync(0xffffffffu, pd, off);
    }
    if (lane == 0) { als[n * NHEAD + w] = ps; ald[n * NHEAD + w] = pd; }
}

// ---------------- per-dst-node softmax + aggregation ------------------------
__global__ void k_gat_aggregate(const float* __restrict__ hsrc,
                                const int* __restrict__ rowptr,
                                const int* __restrict__ srcs,
                                const float* __restrict__ als,
                                const float* __restrict__ ald,
                                const float* __restrict__ bias,
                                float* __restrict__ out) {
    int n = blockIdx.x;
    int t = threadIdx.x;
    int slot = t >> 2;
    int head = t & 3;
    int head2 = t >> 6;

    int p0  = rowptr[n];
    int deg = rowptr[n + 1] - p0;

    __shared__ float red[NHEAD][64];
    __shared__ float sw[64 * NHEAD];
    __shared__ int   ssrc[64];
    __shared__ float smax[NHEAD], sden[NHEAD];

    float aldv = ald[n * NHEAD + head];

    float m = -1e30f;
    for (int j = slot; j < deg; j += 64) {
        int s = srcs[p0 + j];
        float e = als[s * NHEAD + head] + aldv;
        e = (e > 0.f) ? e : 0.2f * e;
        m = fmaxf(m, e);
    }
    red[head][slot] = m;
    __syncthreads();
    for (int off = 32; off >= 1; off >>= 1) {
        if (slot < off) red[head][slot] = fmaxf(red[head][slot], red[head][slot + off]);
        __syncthreads();
    }
    if (t < NHEAD) smax[t] = red[t][0];
    __syncthreads();
    float mx = smax[head];

    float dsum = 0.f;
    for (int j = slot; j < deg; j += 64) {
        int s = srcs[p0 + j];
        float e = als[s * NHEAD + head] + aldv;
        e = (e > 0.f) ? e : 0.2f * e;
        dsum += __expf(e - mx);
    }
    red[head][slot] = dsum;
    __syncthreads();
    for (int off = 32; off >= 1; off >>= 1) {
        if (slot < off) red[head][slot] += red[head][slot + off];
        __syncthreads();
    }
    if (t < NHEAD) sden[t] = red[t][0];
    __syncthreads();

    float invden = 1.f / sden[head];

    float acc = 0.f;
    for (int base = 0; base < deg; base += 64) {
        int j = base + slot;
        if (j < deg) {
            int s = srcs[p0 + j];
            if (head == 0) ssrc[slot] = s;
            float e = als[s * NHEAD + head] + aldv;
            e = (e > 0.f) ? e : 0.2f * e;
            sw[slot * NHEAD + head] = __expf(e - mx) * invden;
        }
        __syncthreads();
        int lim = min(64, deg - base);
#pragma unroll 4
        for (int j2 = 0; j2 < lim; j2++) {
            acc += sw[j2 * NHEAD + head2] * hsrc[(size_t)ssrc[j2] * FDIM + t];
        }
        __syncthreads();
    }

    float o = acc + bias[t];
    o = (o > 0.f) ? o : expm1f(o);
    out[(size_t)n * FDIM + t] = o;
}

// ---------------- launch ----------------------------------------------------
extern "C" void kernel_launch(void* const* d_in, const int* in_sizes, int n_in,
                              void* d_out, int out_size) {
    const float* x     = (const float*)d_in[0];
    const int*   ei    = (const int*)d_in[1];   // int32 (JAX x64 disabled)
    const float* W1    = (const float*)d_in[3];
    const float* asrc1 = (const float*)d_in[4];
    const float* adst1 = (const float*)d_in[5];
    const float* b1    = (const float*)d_in[6];
    const float* W2    = (const float*)d_in[7];
    const float* asrc2 = (const float*)d_in[8];
    const float* adst2 = (const float*)d_in[9];
    const float* b2    = (const float*)d_in[10];
    const float* fcW   = (const float*)d_in[11];
    const float* fcb   = (const float*)d_in[12];
    float* out = (float*)d_out;

    float *t, *h1, *h2, *als, *ald, *wt1, *wt2, *wtfc;
    int *deg, *rowptr, *cursor, *srcs;
    cudaGetSymbolAddress((void**)&t, g_t);
    cudaGetSymbolAddress((void**)&h1, g_h1);
    cudaGetSymbolAddress((void**)&h2, g_h2);
    cudaGetSymbolAddress((void**)&als, g_als);
    cudaGetSymbolAddress((void**)&ald, g_ald);
    cudaGetSymbolAddress((void**)&wt1, g_wt1);
    cudaGetSymbolAddress((void**)&wt2, g_wt2);
    cudaGetSymbolAddress((void**)&wtfc, g_wtfc);
    cudaGetSymbolAddress((void**)&deg, g_deg);
    cudaGetSymbolAddress((void**)&rowptr, g_rowptr);
    cudaGetSymbolAddress((void**)&cursor, g_cursor);
    cudaGetSymbolAddress((void**)&srcs, g_srcs);

    // CSR by dst + weight transposes
    k_init_deg<<<(NNODE + 255) / 256, 256>>>(deg);
    k_count_deg<<<(NEDGE + 255) / 256, 256>>>(ei, deg);
    k_transpose<<<(FDIM * FDIM + 255) / 256, 256>>>(W1, wt1, FDIM, FDIM);
    k_transpose<<<(FDIM * FDIM + 255) / 256, 256>>>(W2, wt2, FDIM, FDIM);
    k_transpose<<<(FDIM * OUTD + 255) / 256, 256>>>(fcW, wtfc, FDIM, OUTD);
    k_scan<<<1, 1024>>>(deg, rowptr, cursor);
    k_scatter<<<(EPAD + 255) / 256, 256>>>(ei, cursor, srcs);

    const int NTILE = (NNODE + 127) / 128;   // 391
    dim3 gbig(NTILE, 2);
    dim3 gfc(NTILE, 1);

    // layer 1
    k_gemm_mma<128, 256><<<gbig, 256>>>(x, wt1, nullptr, t, NNODE);
    k_attn_logits<<<NNODE, 128>>>(t, asrc1, adst1, als, ald);
    k_gat_aggregate<<<NNODE, 256>>>(t, rowptr, srcs, als, ald, b1, h1);

    // layer 2
    k_gemm_mma<128, 256><<<gbig, 256>>>(h1, wt2, nullptr, t, NNODE);
    k_attn_logits<<<NNODE, 128>>>(t, asrc2, adst2, als, ald);
    k_gat_aggregate<<<NNODE, 256>>>(t, rowptr, srcs, als, ald, b2, h2);

    // fc head
    k_gemm_mma<64, 64><<<gfc, 256>>>(h2, wtfc, fcb, out, NNODE);
}

// round 6
// speedup vs baseline: 1.9352x; 1.4145x over previous
#include <cuda_runtime.h>
#include <math.h>
#include <stdint.h>

#define NNODE 50000
#define NEDGE 800000
#define EPAD  (NEDGE + NNODE)
#define FDIM  256
#define NHEAD 4
#define OUTD  64
#define NBLK  ((NNODE + 1023) / 1024)   // 49 scan blocks

// ---------------- scratch ---------------------------------------------------
__device__ __align__(128) float g_t[NNODE * FDIM];
__device__ __align__(128) float g_h1[NNODE * FDIM];
__device__ __align__(128) float g_h2[NNODE * FDIM];
__device__ __align__(16) uint16_t g_w1h[FDIM * FDIM];   // W1^T hi bf16 [N][K]
__device__ __align__(16) uint16_t g_w1l[FDIM * FDIM];
__device__ __align__(16) uint16_t g_w2h[FDIM * FDIM];
__device__ __align__(16) uint16_t g_w2l[FDIM * FDIM];
__device__ __align__(16) uint16_t g_wfh[OUTD * FDIM];
__device__ __align__(16) uint16_t g_wfl[OUTD * FDIM];
__device__ float g_als[NNODE * NHEAD];
__device__ float g_ald[NNODE * NHEAD];
__device__ int   g_deg[NNODE];
__device__ int   g_rowptr[NNODE + 1];
__device__ int   g_cursor[NNODE];
__device__ int   g_srcs[EPAD];
__device__ int   g_bsum[NBLK + 1];
__device__ int   g_boff[NBLK + 1];

__device__ __forceinline__ int clampi(int v, int lo, int hi) {
    return v < lo ? lo : (v > hi ? hi : v);
}
// pack two floats to bf16x2 word: v0 -> bits[15:0], v1 -> bits[31:16]
__device__ __forceinline__ uint32_t pack_bf16x2(float v0, float v1) {
    uint32_t d;
    asm("cvt.rn.bf16x2.f32 %0, %1, %2;" : "=r"(d) : "f"(v1), "f"(v0));
    return d;
}
__device__ __forceinline__ void mma_bf16(float* d, const uint32_t* a, const uint32_t* b) {
    asm volatile(
        "mma.sync.aligned.m16n8k16.row.col.f32.bf16.bf16.f32 "
        "{%0,%1,%2,%3}, {%4,%5,%6,%7}, {%8,%9}, {%0,%1,%2,%3};"
        : "+f"(d[0]), "+f"(d[1]), "+f"(d[2]), "+f"(d[3])
        : "r"(a[0]), "r"(a[1]), "r"(a[2]), "r"(a[3]), "r"(b[0]), "r"(b[1]));
}

// ---------------- CSR construction ------------------------------------------
__global__ void k_init_deg(int* deg) {
    int i = blockIdx.x * blockDim.x + threadIdx.x;
    if (i < NNODE) deg[i] = 1;
}
__global__ void k_count_deg(const int* __restrict__ ei, int* deg) {
    int e = blockIdx.x * blockDim.x + threadIdx.x;
    if (e < NEDGE) atomicAdd(&deg[clampi(ei[NEDGE + e], 0, NNODE - 1)], 1);
}
// phase 1: per-block exclusive scan (warp shuffles), block sums out
__global__ void k_scan1(const int* __restrict__ deg, int* rowptr, int* bsum) {
    int b = blockIdx.x, tid = threadIdx.x;
    int i = b * 1024 + tid;
    int v = (i < NNODE) ? deg[i] : 0;
    int lane = tid & 31, w = tid >> 5;
    int x = v;
#pragma unroll
    for (int off = 1; off < 32; off <<= 1) {
        int y = __shfl_up_sync(0xffffffffu, x, off);
        if (lane >= off) x += y;
    }
    __shared__ int ws[32];
    if (lane == 31) ws[w] = x;
    __syncthreads();
    if (w == 0) {
        int s = ws[lane];
#pragma unroll
        for (int off = 1; off < 32; off <<= 1) {
            int y = __shfl_up_sync(0xffffffffu, s, off);
            if (lane >= off) s += y;
        }
        ws[lane] = s;
    }
    __syncthreads();
    int wo = (w > 0) ? ws[w - 1] : 0;
    int incl = x + wo;
    if (i < NNODE) rowptr[i] = incl - v;   // local exclusive
    if (tid == 1023) bsum[b] = incl;
}
__global__ void k_scan2(const int* __restrict__ bsum, int* boff, int* rowptr) {
    if (threadIdx.x == 0) {
        int s = 0;
        for (int b = 0; b < NBLK; b++) { boff[b] = s; s += bsum[b]; }
        rowptr[NNODE] = s;
    }
}
__global__ void k_scan3(int* rowptr, int* cursor, const int* __restrict__ boff) {
    int i = blockIdx.x * blockDim.x + threadIdx.x;
    if (i < NNODE) {
        int r = rowptr[i] + boff[i >> 10];
        rowptr[i] = r;
        cursor[i] = r;
    }
}
__global__ void k_scatter(const int* __restrict__ ei, int* cursor, int* srcs) {
    int e = blockIdx.x * blockDim.x + threadIdx.x;
    if (e < NEDGE) {
        int s = clampi(ei[e], 0, NNODE - 1);
        int d = clampi(ei[NEDGE + e], 0, NNODE - 1);
        int pos = atomicAdd(&cursor[d], 1);
        if (pos >= 0 && pos < EPAD) srcs[pos] = s;
    } else if (e < EPAD) {
        int i = e - NEDGE;
        int pos = atomicAdd(&cursor[i], 1);
        if (pos >= 0 && pos < EPAD) srcs[pos] = i;
    }
}

// ---------------- weight split/transpose: W[K][N] -> hi/lo bf16 [N][K] ------
__global__ void k_split_w(const float* __restrict__ W, uint16_t* __restrict__ WH,
                          uint16_t* __restrict__ WL, int K, int N) {
    int i = blockIdx.x * blockDim.x + threadIdx.x;
    if (i < K * N) {
        int k = i / N, n = i % N;
        float v = W[i];
        uint32_t hw = pack_bf16x2(v, 0.f);
        float hf = __uint_as_float(hw << 16);
        uint32_t lw = pack_bf16x2(v - hf, 0.f);
        WH[n * K + k] = (uint16_t)(hw & 0xffffu);
        WL[n * K + k] = (uint16_t)(lw & 0xffffu);
    }
}

// ---------------- bf16-split tensor-core GEMM + fused logits ----------------
// C[M,NOUT] = A[M,256] @ B (B pre-split bf16 hi/lo, [NOUT][256] K-major) (+bias)
// 8 warps (4m x 2n), block tile 128 x BN, BK=32. 3 products: hh + hl + lh.
// If als_out: per-warp head logits (head = blockIdx.y*2 + wn, valid for BN=128).
template<int BN, int NOUT>
__global__ void __launch_bounds__(256, 2)
k_gemm_mma(const float* __restrict__ A,
           const uint16_t* __restrict__ BH, const uint16_t* __restrict__ BL,
           const float* __restrict__ bias, float* __restrict__ C, int M,
           const float* __restrict__ a_src, const float* __restrict__ a_dst,
           float* __restrict__ als_out, float* __restrict__ ald_out) {
    constexpr int RS = 40;
    constexpr int WN = BN / 2;
    constexpr int NT = WN / 8;
    constexpr int A_F4 = 128 * 8 / 256;      // 4 float4 per thread
    constexpr int B_U4 = BN * 4 / 256;       // uint4 (8 bf16) per thread per buf

    __shared__ __align__(16) uint16_t sAh[128 * RS];
    __shared__ __align__(16) uint16_t sAl[128 * RS];
    __shared__ __align__(16) uint16_t sBh[BN * RS];
    __shared__ __align__(16) uint16_t sBl[BN * RS];

    const int tid  = threadIdx.x;
    const int wid  = tid >> 5, lane = tid & 31;
    const int wm   = wid & 3, wn = wid >> 2;
    const int g    = lane >> 2, tq = lane & 3;
    const int brow = blockIdx.x * 128;
    const int bcol = blockIdx.y * BN;

    float acc[2][NT][4];
#pragma unroll
    for (int mt = 0; mt < 2; mt++)
#pragma unroll
        for (int nt = 0; nt < NT; nt++)
#pragma unroll
            for (int r = 0; r < 4; r++) acc[mt][nt][r] = 0.f;

    float4 aS[A_F4];
    uint4  bSh[B_U4], bSl[B_U4];

    auto load_regs = [&](int k0) {
#pragma unroll
        for (int u = 0; u < A_F4; u++) {
            int q = tid + u * 256;
            int row = q >> 3, f4 = q & 7;
            int gr = brow + row;
            aS[u] = make_float4(0.f, 0.f, 0.f, 0.f);
            if (gr < M) aS[u] = *reinterpret_cast<const float4*>(&A[(size_t)gr * 256 + k0 + f4 * 4]);
        }
#pragma unroll
        for (int u = 0; u < B_U4; u++) {
            int q = tid + u * 256;
            int row = q >> 2, c8 = q & 3;
            size_t gi = (size_t)(bcol + row) * 256 + k0 + c8 * 8;
            bSh[u] = *reinterpret_cast<const uint4*>(&BH[gi]);
            bSl[u] = *reinterpret_cast<const uint4*>(&BL[gi]);
        }
    };
    auto split_store = [](uint16_t* hb, uint16_t* lb, int idx, float v0, float v1) {
        uint32_t hw = pack_bf16x2(v0, v1);
        float f0 = __uint_as_float(hw << 16);
        float f1 = __uint_as_float(hw & 0xffff0000u);
        uint32_t lw = pack_bf16x2(v0 - f0, v1 - f1);
        *reinterpret_cast<uint32_t*>(hb + idx) = hw;
        *reinterpret_cast<uint32_t*>(lb + idx) = lw;
    };
    auto store_smem = [&]() {
#pragma unroll
        for (int u = 0; u < A_F4; u++) {
            int q = tid + u * 256;
            int row = q >> 3, f4 = q & 7;
            int idx = row * RS + f4 * 4;
            split_store(sAh, sAl, idx,     aS[u].x, aS[u].y);
            split_store(sAh, sAl, idx + 2, aS[u].z, aS[u].w);
        }
#pragma unroll
        for (int u = 0; u < B_U4; u++) {
            int q = tid + u * 256;
            int row = q >> 2, c8 = q & 3;
            int idx = row * RS + c8 * 8;
            *reinterpret_cast<uint4*>(&sBh[idx]) = bSh[u];
            *reinterpret_cast<uint4*>(&sBl[idx]) = bSl[u];
        }
    };

    load_regs(0);
    store_smem();
    __syncthreads();

    for (int t = 0; t < 8; t++) {
        if (t + 1 < 8) load_regs((t + 1) * 32);

#pragma unroll
        for (int ks = 0; ks < 2; ks++) {
            const int kb = ks * 16;
            uint32_t ah[2][4], al[2][4];
#pragma unroll
            for (int mt = 0; mt < 2; mt++) {
                int r0 = (wm * 32 + mt * 16 + g) * RS;
                int r8 = r0 + 8 * RS;
                ah[mt][0] = *reinterpret_cast<const uint32_t*>(&sAh[r0 + kb + tq * 2]);
                ah[mt][1] = *reinterpret_cast<const uint32_t*>(&sAh[r8 + kb + tq * 2]);
                ah[mt][2] = *reinterpret_cast<const uint32_t*>(&sAh[r0 + kb + 8 + tq * 2]);
                ah[mt][3] = *reinterpret_cast<const uint32_t*>(&sAh[r8 + kb + 8 + tq * 2]);
                al[mt][0] = *reinterpret_cast<const uint32_t*>(&sAl[r0 + kb + tq * 2]);
                al[mt][1] = *reinterpret_cast<const uint32_t*>(&sAl[r8 + kb + tq * 2]);
                al[mt][2] = *reinterpret_cast<const uint32_t*>(&sAl[r0 + kb + 8 + tq * 2]);
                al[mt][3] = *reinterpret_cast<const uint32_t*>(&sAl[r8 + kb + 8 + tq * 2]);
            }
#pragma unroll
            for (int nt = 0; nt < NT; nt++) {
                int nr = (wn * WN + nt * 8 + g) * RS;
                uint32_t bh[2], bl[2];
                bh[0] = *reinterpret_cast<const uint32_t*>(&sBh[nr + kb + tq * 2]);
                bh[1] = *reinterpret_cast<const uint32_t*>(&sBh[nr + kb + 8 + tq * 2]);
                bl[0] = *reinterpret_cast<const uint32_t*>(&sBl[nr + kb + tq * 2]);
                bl[1] = *reinterpret_cast<const uint32_t*>(&sBl[nr + kb + 8 + tq * 2]);
#pragma unroll
                for (int mt = 0; mt < 2; mt++) {
                    mma_bf16(acc[mt][nt], ah[mt], bh);
                    mma_bf16(acc[mt][nt], ah[mt], bl);
                    mma_bf16(acc[mt][nt], al[mt], bh);
                }
            }
        }

        if (t + 1 < 8) {
            __syncthreads();
            store_smem();
            __syncthreads();
        }
    }

    // epilogue: C stores (fragment-direct float2)
#pragma unroll
    for (int mt = 0; mt < 2; mt++) {
        int r0 = brow + wm * 32 + mt * 16 + g;
        int r1 = r0 + 8;
#pragma unroll
        for (int nt = 0; nt < NT; nt++) {
            int col = bcol + wn * WN + nt * 8 + tq * 2;
            float b0 = 0.f, b1 = 0.f;
            if (bias) { b0 = bias[col]; b1 = bias[col + 1]; }
            if (r0 < M)
                *reinterpret_cast<float2*>(&C[(size_t)r0 * NOUT + col]) =
                    make_float2(acc[mt][nt][0] + b0, acc[mt][nt][1] + b1);
            if (r1 < M)
                *reinterpret_cast<float2*>(&C[(size_t)r1 * NOUT + col]) =
                    make_float2(acc[mt][nt][2] + b0, acc[mt][nt][3] + b1);
        }
    }

    // fused attention logits (BN==128 path): head = blockIdx.y*2 + wn
    if (als_out) {
        int head = blockIdx.y * 2 + wn;
#pragma unroll
        for (int mt = 0; mt < 2; mt++) {
#pragma unroll
            for (int half = 0; half < 2; half++) {
                float ps = 0.f, pd = 0.f;
#pragma unroll
                for (int nt = 0; nt < NT; nt++) {
                    int col = bcol + wn * WN + nt * 8 + tq * 2;
                    float a0 = acc[mt][nt][half * 2 + 0];
                    float a1 = acc[mt][nt][half * 2 + 1];
                    ps += a0 * a_src[col] + a1 * a_src[col + 1];
                    pd += a0 * a_dst[col] + a1 * a_dst[col + 1];
                }
                ps += __shfl_xor_sync(0xffffffffu, ps, 1);
                pd += __shfl_xor_sync(0xffffffffu, pd, 1);
                ps += __shfl_xor_sync(0xffffffffu, ps, 2);
                pd += __shfl_xor_sync(0xffffffffu, pd, 2);
                int row = brow + wm * 32 + mt * 16 + g + half * 8;
                if (tq == 0 && row < M) {
                    als_out[row * NHEAD + head] = ps;
                    ald_out[row * NHEAD + head] = pd;
                }
            }
        }
    }
}

// ---------------- single-pass per-dst softmax aggregation -------------------
// softmax is shift-invariant: skip max pass, normalize by sum(exp) at the end.
__global__ void k_gat_aggregate(const float* __restrict__ hsrc,
                                const int* __restrict__ rowptr,
                                const int* __restrict__ srcs,
                                const float* __restrict__ als,
                                const float* __restrict__ ald,
                                const float* __restrict__ bias,
                                float* __restrict__ out) {
    int n = blockIdx.x;
    int t = threadIdx.x;
    int slot = t >> 2;       // 0..63 (edge slot role)
    int head = t & 3;        // head role for weight computation
    int head2 = t >> 6;      // channel-owner head (channel = t)

    int p0  = rowptr[n];
    int deg = rowptr[n + 1] - p0;

    __shared__ float sw[64 * NHEAD];
    __shared__ int   ssrc[64];
    __shared__ float red[NHEAD][64];
    __shared__ float sden[NHEAD];

    float aldv = ald[n * NHEAD + head];
    float acc = 0.f;
    float dsum = 0.f;

    for (int base = 0; base < deg; base += 64) {
        int j = base + slot;
        if (j < deg) {
            int s = srcs[p0 + j];
            if (head == 0) ssrc[slot] = s;
            float e = als[s * NHEAD + head] + aldv;
            e = (e > 0.f) ? e : 0.2f * e;
            float w = __expf(e);
            sw[slot * NHEAD + head] = w;
            dsum += w;
        }
        __syncthreads();
        int lim = min(64, deg - base);
#pragma unroll 4
        for (int j2 = 0; j2 < lim; j2++) {
            acc += sw[j2 * NHEAD + head2] * hsrc[(size_t)ssrc[j2] * FDIM + t];
        }
        __syncthreads();
    }

    red[head][slot] = dsum;
    __syncthreads();
    for (int off = 32; off >= 1; off >>= 1) {
        if (slot < off) red[head][slot] += red[head][slot + off];
        __syncthreads();
    }
    if (t < NHEAD) sden[t] = red[t][0];
    __syncthreads();

    float o = acc / sden[head2] + bias[t];
    o = (o > 0.f) ? o : expm1f(o);   // ELU
    out[(size_t)n * FDIM + t] = o;
}

// ---------------- launch ----------------------------------------------------
extern "C" void kernel_launch(void* const* d_in, const int* in_sizes, int n_in,
                              void* d_out, int out_size) {
    const float* x     = (const float*)d_in[0];
    const int*   ei    = (const int*)d_in[1];   // int32 (JAX x64 disabled)
    const float* W1    = (const float*)d_in[3];
    const float* asrc1 = (const float*)d_in[4];
    const float* adst1 = (const float*)d_in[5];
    const float* b1    = (const float*)d_in[6];
    const float* W2    = (const float*)d_in[7];
    const float* asrc2 = (const float*)d_in[8];
    const float* adst2 = (const float*)d_in[9];
    const float* b2    = (const float*)d_in[10];
    const float* fcW   = (const float*)d_in[11];
    const float* fcb   = (const float*)d_in[12];
    float* out = (float*)d_out;

    float *t, *h1, *h2, *als, *ald;
    uint16_t *w1h, *w1l, *w2h, *w2l, *wfh, *wfl;
    int *deg, *rowptr, *cursor, *srcs, *bsum, *boff;
    cudaGetSymbolAddress((void**)&t, g_t);
    cudaGetSymbolAddress((void**)&h1, g_h1);
    cudaGetSymbolAddress((void**)&h2, g_h2);
    cudaGetSymbolAddress((void**)&als, g_als);
    cudaGetSymbolAddress((void**)&ald, g_ald);
    cudaGetSymbolAddress((void**)&w1h, g_w1h);
    cudaGetSymbolAddress((void**)&w1l, g_w1l);
    cudaGetSymbolAddress((void**)&w2h, g_w2h);
    cudaGetSymbolAddress((void**)&w2l, g_w2l);
    cudaGetSymbolAddress((void**)&wfh, g_wfh);
    cudaGetSymbolAddress((void**)&wfl, g_wfl);
    cudaGetSymbolAddress((void**)&deg, g_deg);
    cudaGetSymbolAddress((void**)&rowptr, g_rowptr);
    cudaGetSymbolAddress((void**)&cursor, g_cursor);
    cudaGetSymbolAddress((void**)&srcs, g_srcs);
    cudaGetSymbolAddress((void**)&bsum, g_bsum);
    cudaGetSymbolAddress((void**)&boff, g_boff);

    // CSR + weight splits
    k_init_deg<<<(NNODE + 255) / 256, 256>>>(deg);
    k_count_deg<<<(NEDGE + 255) / 256, 256>>>(ei, deg);
    k_split_w<<<(FDIM * FDIM + 255) / 256, 256>>>(W1, w1h, w1l, FDIM, FDIM);
    k_split_w<<<(FDIM * FDIM + 255) / 256, 256>>>(W2, w2h, w2l, FDIM, FDIM);
    k_split_w<<<(FDIM * OUTD + 255) / 256, 256>>>(fcW, wfh, wfl, FDIM, OUTD);
    k_scan1<<<NBLK, 1024>>>(deg, rowptr, bsum);
    k_scan2<<<1, 32>>>(bsum, boff, rowptr);
    k_scan3<<<NBLK, 1024>>>(rowptr, cursor, boff);
    k_scatter<<<(EPAD + 255) / 256, 256>>>(ei, cursor, srcs);

    const int NTILE = (NNODE + 127) / 128;   // 391
    dim3 gbig(NTILE, 2);
    dim3 gfc(NTILE, 1);

    // layer 1 (GEMM + fused logits)
    k_gemm_mma<128, 256><<<gbig, 256>>>(x, w1h, w1l, nullptr, t, NNODE,
                                        asrc1, adst1, als, ald);
    k_gat_aggregate<<<NNODE, 256>>>(t, rowptr, srcs, als, ald, b1, h1);

    // layer 2
    k_gemm_mma<128, 256><<<gbig, 256>>>(h1, w2h, w2l, nullptr, t, NNODE,
                                        asrc2, adst2, als, ald);
    k_gat_aggregate<<<NNODE, 256>>>(t, rowptr, srcs, als, ald, b2, h2);

    // fc head
    k_gemm_mma<64, 64><<<gfc, 256>>>(h2, wfh, wfl, fcb, out, NNODE,
                                     nullptr, nullptr, nullptr, nullptr);
}

// round 7
// speedup vs baseline: 2.4683x; 1.2755x over previous
#include <cuda_runtime.h>
#include <math.h>
#include <stdint.h>

#define NNODE 50000
#define NEDGE 800000
#define EPAD  (NEDGE + NNODE)
#define FDIM  256
#define NHEAD 4
#define OUTD  64
#define NBLK  ((NNODE + 1023) / 1024)   // 49 scan blocks

// ---------------- scratch ---------------------------------------------------
__device__ __align__(128) float g_t[NNODE * FDIM];        // GEMM fp32 out
__device__ __align__(16) uint16_t g_h1h[NNODE * FDIM];    // layer-1 h, bf16 hi
__device__ __align__(16) uint16_t g_h1l[NNODE * FDIM];    // layer-1 h, bf16 lo
__device__ __align__(16) uint16_t g_h2h[NNODE * FDIM];
__device__ __align__(16) uint16_t g_h2l[NNODE * FDIM];
__device__ __align__(16) uint16_t g_w1h[FDIM * FDIM];     // W^T hi bf16 [N][K]
__device__ __align__(16) uint16_t g_w1l[FDIM * FDIM];
__device__ __align__(16) uint16_t g_w2h[FDIM * FDIM];
__device__ __align__(16) uint16_t g_w2l[FDIM * FDIM];
__device__ __align__(16) uint16_t g_wfh[OUTD * FDIM];
__device__ __align__(16) uint16_t g_wfl[OUTD * FDIM];
__device__ float g_als[NNODE * NHEAD];
__device__ float g_ald[NNODE * NHEAD];
__device__ int   g_deg[NNODE];
__device__ int   g_rowptr[NNODE + 1];
__device__ int   g_cursor[NNODE];
__device__ int   g_srcs[EPAD];
__device__ int   g_bsum[NBLK + 1];
__device__ int   g_boff[NBLK + 1];

__device__ __forceinline__ int clampi(int v, int lo, int hi) {
    return v < lo ? lo : (v > hi ? hi : v);
}
// pack two floats to bf16x2 word: v0 -> bits[15:0], v1 -> bits[31:16]
__device__ __forceinline__ uint32_t pack_bf16x2(float v0, float v1) {
    uint32_t d;
    asm("cvt.rn.bf16x2.f32 %0, %1, %2;" : "=r"(d) : "f"(v1), "f"(v0));
    return d;
}
__device__ __forceinline__ void mma_bf16(float* d, const uint32_t* a, const uint32_t* b) {
    asm volatile(
        "mma.sync.aligned.m16n8k16.row.col.f32.bf16.bf16.f32 "
        "{%0,%1,%2,%3}, {%4,%5,%6,%7}, {%8,%9}, {%0,%1,%2,%3};"
        : "+f"(d[0]), "+f"(d[1]), "+f"(d[2]), "+f"(d[3])
        : "r"(a[0]), "r"(a[1]), "r"(a[2]), "r"(a[3]), "r"(b[0]), "r"(b[1]));
}

// ---------------- CSR construction ------------------------------------------
__global__ void k_init_deg(int* deg) {
    int i = blockIdx.x * blockDim.x + threadIdx.x;
    if (i < NNODE) deg[i] = 1;
}
__global__ void k_count_deg(const int* __restrict__ ei, int* deg) {
    int e = blockIdx.x * blockDim.x + threadIdx.x;
    if (e < NEDGE) atomicAdd(&deg[clampi(ei[NEDGE + e], 0, NNODE - 1)], 1);
}
__global__ void k_scan1(const int* __restrict__ deg, int* rowptr, int* bsum) {
    int b = blockIdx.x, tid = threadIdx.x;
    int i = b * 1024 + tid;
    int v = (i < NNODE) ? deg[i] : 0;
    int lane = tid & 31, w = tid >> 5;
    int x = v;
#pragma unroll
    for (int off = 1; off < 32; off <<= 1) {
        int y = __shfl_up_sync(0xffffffffu, x, off);
        if (lane >= off) x += y;
    }
    __shared__ int ws[32];
    if (lane == 31) ws[w] = x;
    __syncthreads();
    if (w == 0) {
        int s = ws[lane];
#pragma unroll
        for (int off = 1; off < 32; off <<= 1) {
            int y = __shfl_up_sync(0xffffffffu, s, off);
            if (lane >= off) s += y;
        }
        ws[lane] = s;
    }
    __syncthreads();
    int wo = (w > 0) ? ws[w - 1] : 0;
    int incl = x + wo;
    if (i < NNODE) rowptr[i] = incl - v;
    if (tid == 1023) bsum[b] = incl;
}
__global__ void k_scan2(const int* __restrict__ bsum, int* boff, int* rowptr) {
    if (threadIdx.x == 0) {
        int s = 0;
        for (int b = 0; b < NBLK; b++) { boff[b] = s; s += bsum[b]; }
        rowptr[NNODE] = s;
    }
}
__global__ void k_scan3(int* rowptr, int* cursor, const int* __restrict__ boff) {
    int i = blockIdx.x * blockDim.x + threadIdx.x;
    if (i < NNODE) {
        int r = rowptr[i] + boff[i >> 10];
        rowptr[i] = r;
        cursor[i] = r;
    }
}
__global__ void k_scatter(const int* __restrict__ ei, int* cursor, int* srcs) {
    int e = blockIdx.x * blockDim.x + threadIdx.x;
    if (e < NEDGE) {
        int s = clampi(ei[e], 0, NNODE - 1);
        int d = clampi(ei[NEDGE + e], 0, NNODE - 1);
        int pos = atomicAdd(&cursor[d], 1);
        if (pos >= 0 && pos < EPAD) srcs[pos] = s;
    } else if (e < EPAD) {
        int i = e - NEDGE;
        int pos = atomicAdd(&cursor[i], 1);
        if (pos >= 0 && pos < EPAD) srcs[pos] = i;
    }
}

// ---------------- weight split/transpose: W[K][N] -> hi/lo bf16 [N][K] ------
__global__ void k_split_w(const float* __restrict__ W, uint16_t* __restrict__ WH,
                          uint16_t* __restrict__ WL, int K, int N) {
    int i = blockIdx.x * blockDim.x + threadIdx.x;
    if (i < K * N) {
        int k = i / N, n = i % N;
        float v = W[i];
        uint32_t hw = pack_bf16x2(v, 0.f);
        float hf = __uint_as_float(hw << 16);
        uint32_t lw = pack_bf16x2(v - hf, 0.f);
        WH[n * K + k] = (uint16_t)(hw & 0xffffu);
        WL[n * K + k] = (uint16_t)(lw & 0xffffu);
    }
}

// ---------------- bf16-split tensor-core GEMM + fused logits ----------------
// C[M,NOUT] = A[M,256] @ B (B pre-split bf16 hi/lo, [NOUT][256] K-major) (+bias)
// PRESPLIT: A given as bf16 hi/lo arrays [M][256]; else fp32, split in-kernel.
template<int BN, int NOUT, bool PRESPLIT>
__global__ void __launch_bounds__(256, 2)
k_gemm_mma(const float* __restrict__ A,
           const uint16_t* __restrict__ AH, const uint16_t* __restrict__ AL,
           const uint16_t* __restrict__ BH, const uint16_t* __restrict__ BL,
           const float* __restrict__ bias, float* __restrict__ C, int M,
           const float* __restrict__ a_src, const float* __restrict__ a_dst,
           float* __restrict__ als_out, float* __restrict__ ald_out) {
    constexpr int RS = 40;
    constexpr int WN = BN / 2;
    constexpr int NT = WN / 8;
    constexpr int A_F4 = 4;                  // fp32 path: 4 float4 per thread
    constexpr int A_U4 = 2;                  // presplit: 2 uint4 per array
    constexpr int B_U4 = BN * 4 / 256;

    __shared__ __align__(16) uint16_t sAh[128 * RS];
    __shared__ __align__(16) uint16_t sAl[128 * RS];
    __shared__ __align__(16) uint16_t sBh[BN * RS];
    __shared__ __align__(16) uint16_t sBl[BN * RS];

    const int tid  = threadIdx.x;
    const int wid  = tid >> 5, lane = tid & 31;
    const int wm   = wid & 3, wn = wid >> 2;
    const int g    = lane >> 2, tq = lane & 3;
    const int brow = blockIdx.x * 128;
    const int bcol = blockIdx.y * BN;

    float acc[2][NT][4];
#pragma unroll
    for (int mt = 0; mt < 2; mt++)
#pragma unroll
        for (int nt = 0; nt < NT; nt++)
#pragma unroll
            for (int r = 0; r < 4; r++) acc[mt][nt][r] = 0.f;

    float4 aS[A_F4];
    uint4  aSh[A_U4], aSl[A_U4];
    uint4  bSh[B_U4], bSl[B_U4];

    auto load_regs = [&](int k0) {
        if (PRESPLIT) {
#pragma unroll
            for (int u = 0; u < A_U4; u++) {
                int q = tid + u * 256;
                int row = q >> 2, c8 = q & 3;
                int gr = brow + row;
                if (gr < M) {
                    size_t gi = (size_t)gr * 256 + k0 + c8 * 8;
                    aSh[u] = *reinterpret_cast<const uint4*>(&AH[gi]);
                    aSl[u] = *reinterpret_cast<const uint4*>(&AL[gi]);
                } else {
                    aSh[u] = make_uint4(0, 0, 0, 0);
                    aSl[u] = make_uint4(0, 0, 0, 0);
                }
            }
        } else {
#pragma unroll
            for (int u = 0; u < A_F4; u++) {
                int q = tid + u * 256;
                int row = q >> 3, f4 = q & 7;
                int gr = brow + row;
                aS[u] = make_float4(0.f, 0.f, 0.f, 0.f);
                if (gr < M) aS[u] = *reinterpret_cast<const float4*>(&A[(size_t)gr * 256 + k0 + f4 * 4]);
            }
        }
#pragma unroll
        for (int u = 0; u < B_U4; u++) {
            int q = tid + u * 256;
            int row = q >> 2, c8 = q & 3;
            size_t gi = (size_t)(bcol + row) * 256 + k0 + c8 * 8;
            bSh[u] = *reinterpret_cast<const uint4*>(&BH[gi]);
            bSl[u] = *reinterpret_cast<const uint4*>(&BL[gi]);
        }
    };
    auto split_store = [](uint16_t* hb, uint16_t* lb, int idx, float v0, float v1) {
        uint32_t hw = pack_bf16x2(v0, v1);
        float f0 = __uint_as_float(hw << 16);
        float f1 = __uint_as_float(hw & 0xffff0000u);
        uint32_t lw = pack_bf16x2(v0 - f0, v1 - f1);
        *reinterpret_cast<uint32_t*>(hb + idx) = hw;
        *reinterpret_cast<uint32_t*>(lb + idx) = lw;
    };
    auto store_smem = [&]() {
        if (PRESPLIT) {
#pragma unroll
            for (int u = 0; u < A_U4; u++) {
                int q = tid + u * 256;
                int row = q >> 2, c8 = q & 3;
                int idx = row * RS + c8 * 8;
                *reinterpret_cast<uint4*>(&sAh[idx]) = aSh[u];
                *reinterpret_cast<uint4*>(&sAl[idx]) = aSl[u];
            }
        } else {
#pragma unroll
            for (int u = 0; u < A_F4; u++) {
                int q = tid + u * 256;
                int row = q >> 3, f4 = q & 7;
                int idx = row * RS + f4 * 4;
                split_store(sAh, sAl, idx,     aS[u].x, aS[u].y);
                split_store(sAh, sAl, idx + 2, aS[u].z, aS[u].w);
            }
        }
#pragma unroll
        for (int u = 0; u < B_U4; u++) {
            int q = tid + u * 256;
            int row = q >> 2, c8 = q & 3;
            int idx = row * RS + c8 * 8;
            *reinterpret_cast<uint4*>(&sBh[idx]) = bSh[u];
            *reinterpret_cast<uint4*>(&sBl[idx]) = bSl[u];
        }
    };

    load_regs(0);
    store_smem();
    __syncthreads();

    for (int t = 0; t < 8; t++) {
        if (t + 1 < 8) load_regs((t + 1) * 32);

#pragma unroll
        for (int ks = 0; ks < 2; ks++) {
            const int kb = ks * 16;
            uint32_t ah[2][4], al[2][4];
#pragma unroll
            for (int mt = 0; mt < 2; mt++) {
                int r0 = (wm * 32 + mt * 16 + g) * RS;
                int r8 = r0 + 8 * RS;
                ah[mt][0] = *reinterpret_cast<const uint32_t*>(&sAh[r0 + kb + tq * 2]);
                ah[mt][1] = *reinterpret_cast<const uint32_t*>(&sAh[r8 + kb + tq * 2]);
                ah[mt][2] = *reinterpret_cast<const uint32_t*>(&sAh[r0 + kb + 8 + tq * 2]);
                ah[mt][3] = *reinterpret_cast<const uint32_t*>(&sAh[r8 + kb + 8 + tq * 2]);
                al[mt][0] = *reinterpret_cast<const uint32_t*>(&sAl[r0 + kb + tq * 2]);
                al[mt][1] = *reinterpret_cast<const uint32_t*>(&sAl[r8 + kb + tq * 2]);
                al[mt][2] = *reinterpret_cast<const uint32_t*>(&sAl[r0 + kb + 8 + tq * 2]);
                al[mt][3] = *reinterpret_cast<const uint32_t*>(&sAl[r8 + kb + 8 + tq * 2]);
            }
#pragma unroll
            for (int nt = 0; nt < NT; nt++) {
                int nr = (wn * WN + nt * 8 + g) * RS;
                uint32_t bh[2], bl[2];
                bh[0] = *reinterpret_cast<const uint32_t*>(&sBh[nr + kb + tq * 2]);
                bh[1] = *reinterpret_cast<const uint32_t*>(&sBh[nr + kb + 8 + tq * 2]);
                bl[0] = *reinterpret_cast<const uint32_t*>(&sBl[nr + kb + tq * 2]);
                bl[1] = *reinterpret_cast<const uint32_t*>(&sBl[nr + kb + 8 + tq * 2]);
#pragma unroll
                for (int mt = 0; mt < 2; mt++) {
                    mma_bf16(acc[mt][nt], ah[mt], bh);
                    mma_bf16(acc[mt][nt], ah[mt], bl);
                    mma_bf16(acc[mt][nt], al[mt], bh);
                }
            }
        }

        if (t + 1 < 8) {
            __syncthreads();
            store_smem();
            __syncthreads();
        }
    }

    // epilogue: C stores (fragment-direct float2)
#pragma unroll
    for (int mt = 0; mt < 2; mt++) {
        int r0 = brow + wm * 32 + mt * 16 + g;
        int r1 = r0 + 8;
#pragma unroll
        for (int nt = 0; nt < NT; nt++) {
            int col = bcol + wn * WN + nt * 8 + tq * 2;
            float b0 = 0.f, b1 = 0.f;
            if (bias) { b0 = bias[col]; b1 = bias[col + 1]; }
            if (r0 < M)
                *reinterpret_cast<float2*>(&C[(size_t)r0 * NOUT + col]) =
                    make_float2(acc[mt][nt][0] + b0, acc[mt][nt][1] + b1);
            if (r1 < M)
                *reinterpret_cast<float2*>(&C[(size_t)r1 * NOUT + col]) =
                    make_float2(acc[mt][nt][2] + b0, acc[mt][nt][3] + b1);
        }
    }

    // fused attention logits (BN==128): head = blockIdx.y*2 + wn
    if (als_out) {
        int head = blockIdx.y * 2 + wn;
#pragma unroll
        for (int mt = 0; mt < 2; mt++) {
#pragma unroll
            for (int half = 0; half < 2; half++) {
                float ps = 0.f, pd = 0.f;
#pragma unroll
                for (int nt = 0; nt < NT; nt++) {
                    int col = bcol + wn * WN + nt * 8 + tq * 2;
                    float a0 = acc[mt][nt][half * 2 + 0];
                    float a1 = acc[mt][nt][half * 2 + 1];
                    ps += a0 * a_src[col] + a1 * a_src[col + 1];
                    pd += a0 * a_dst[col] + a1 * a_dst[col + 1];
                }
                ps += __shfl_xor_sync(0xffffffffu, ps, 1);
                pd += __shfl_xor_sync(0xffffffffu, pd, 1);
                ps += __shfl_xor_sync(0xffffffffu, ps, 2);
                pd += __shfl_xor_sync(0xffffffffu, pd, 2);
                int row = brow + wm * 32 + mt * 16 + g + half * 8;
                if (tq == 0 && row < M) {
                    als_out[row * NHEAD + head] = ps;
                    ald_out[row * NHEAD + head] = pd;
                }
            }
        }
    }
}

// ---------------- single-pass aggregation, float2, writes bf16 split --------
// 128 threads per node: thread t owns channels {2t, 2t+1}; warp w owns head w.
__global__ void __launch_bounds__(128)
k_gat_aggregate(const float* __restrict__ hsrc,
                const int* __restrict__ rowptr,
                const int* __restrict__ srcs,
                const float* __restrict__ als,
                const float* __restrict__ ald,
                const float* __restrict__ bias,
                uint16_t* __restrict__ outh, uint16_t* __restrict__ outl) {
    int n = blockIdx.x;
    int t = threadIdx.x;
    int c2 = t;              // channel-pair index 0..127
    int head2 = t >> 5;      // channel-owner head (warp id)
    int slot = t >> 2;       // edge slot 0..31
    int head = t & 3;        // head role for weight computation

    int p0  = rowptr[n];
    int deg = rowptr[n + 1] - p0;

    __shared__ float sw[32 * NHEAD];
    __shared__ int   ssrc[32];
    __shared__ float red[NHEAD][32];
    __shared__ float sden[NHEAD];

    float aldv = ald[n * NHEAD + head];
    float accx = 0.f, accy = 0.f;
    float dsum = 0.f;

    const float2* h2 = reinterpret_cast<const float2*>(hsrc);

    for (int base = 0; base < deg; base += 32) {
        int j = base + slot;
        if (j < deg) {
            int s = srcs[p0 + j];
            if (head == 0) ssrc[slot] = s;
            float e = als[s * NHEAD + head] + aldv;
            e = (e > 0.f) ? e : 0.2f * e;
            float w = __expf(e);
            sw[slot * NHEAD + head] = w;
            dsum += w;
        }
        __syncthreads();
        int lim = min(32, deg - base);
#pragma unroll 4
        for (int j2 = 0; j2 < lim; j2++) {
            float w = sw[j2 * NHEAD + head2];
            float2 v = h2[(size_t)ssrc[j2] * 128 + c2];
            accx += w * v.x;
            accy += w * v.y;
        }
        __syncthreads();
    }

    red[head][slot] = dsum;
    __syncthreads();
    for (int off = 16; off >= 1; off >>= 1) {
        if (slot < off) red[head][slot] += red[head][slot + off];
        __syncthreads();
    }
    if (t < NHEAD) sden[t] = red[t][0];
    __syncthreads();

    float inv = 1.f / sden[head2];
    float o0 = accx * inv + bias[2 * c2];
    float o1 = accy * inv + bias[2 * c2 + 1];
    o0 = (o0 > 0.f) ? o0 : expm1f(o0);
    o1 = (o1 > 0.f) ? o1 : expm1f(o1);

    uint32_t hw = pack_bf16x2(o0, o1);
    float f0 = __uint_as_float(hw << 16);
    float f1 = __uint_as_float(hw & 0xffff0000u);
    uint32_t lw = pack_bf16x2(o0 - f0, o1 - f1);
    reinterpret_cast<uint32_t*>(outh)[(size_t)n * 128 + c2] = hw;
    reinterpret_cast<uint32_t*>(outl)[(size_t)n * 128 + c2] = lw;
}

// ---------------- launch ----------------------------------------------------
extern "C" void kernel_launch(void* const* d_in, const int* in_sizes, int n_in,
                              void* d_out, int out_size) {
    const float* x     = (const float*)d_in[0];
    const int*   ei    = (const int*)d_in[1];   // int32 (JAX x64 disabled)
    const float* W1    = (const float*)d_in[3];
    const float* asrc1 = (const float*)d_in[4];
    const float* adst1 = (const float*)d_in[5];
    const float* b1    = (const float*)d_in[6];
    const float* W2    = (const float*)d_in[7];
    const float* asrc2 = (const float*)d_in[8];
    const float* adst2 = (const float*)d_in[9];
    const float* b2    = (const float*)d_in[10];
    const float* fcW   = (const float*)d_in[11];
    const float* fcb   = (const float*)d_in[12];
    float* out = (float*)d_out;

    float *t, *als, *ald;
    uint16_t *h1h, *h1l, *h2h, *h2l;
    uint16_t *w1h, *w1l, *w2h, *w2l, *wfh, *wfl;
    int *deg, *rowptr, *cursor, *srcs, *bsum, *boff;
    cudaGetSymbolAddress((void**)&t, g_t);
    cudaGetSymbolAddress((void**)&h1h, g_h1h);
    cudaGetSymbolAddress((void**)&h1l, g_h1l);
    cudaGetSymbolAddress((void**)&h2h, g_h2h);
    cudaGetSymbolAddress((void**)&h2l, g_h2l);
    cudaGetSymbolAddress((void**)&als, g_als);
    cudaGetSymbolAddress((void**)&ald, g_ald);
    cudaGetSymbolAddress((void**)&w1h, g_w1h);
    cudaGetSymbolAddress((void**)&w1l, g_w1l);
    cudaGetSymbolAddress((void**)&w2h, g_w2h);
    cudaGetSymbolAddress((void**)&w2l, g_w2l);
    cudaGetSymbolAddress((void**)&wfh, g_wfh);
    cudaGetSymbolAddress((void**)&wfl, g_wfl);
    cudaGetSymbolAddress((void**)&deg, g_deg);
    cudaGetSymbolAddress((void**)&rowptr, g_rowptr);
    cudaGetSymbolAddress((void**)&cursor, g_cursor);
    cudaGetSymbolAddress((void**)&srcs, g_srcs);
    cudaGetSymbolAddress((void**)&bsum, g_bsum);
    cudaGetSymbolAddress((void**)&boff, g_boff);

    const int NTILE = (NNODE + 127) / 128;   // 391
    dim3 gbig(NTILE, 2);
    dim3 gfc(NTILE, 1);

    // launches 0-4 (prep that gemm1 needs, plus CSR kernels w/o deps on gemm)
    k_split_w<<<(FDIM * FDIM + 255) / 256, 256>>>(W1, w1h, w1l, FDIM, FDIM);
    k_split_w<<<(FDIM * FDIM + 255) / 256, 256>>>(W2, w2h, w2l, FDIM, FDIM);
    k_split_w<<<(FDIM * OUTD + 255) / 256, 256>>>(fcW, wfh, wfl, FDIM, OUTD);
    k_init_deg<<<(NNODE + 255) / 256, 256>>>(deg);
    k_count_deg<<<(NEDGE + 255) / 256, 256>>>(ei, deg);

    // launch 5: layer-1 GEMM (profiled by ncu -s 5 -c 1)
    k_gemm_mma<128, 256, false><<<gbig, 256>>>(x, nullptr, nullptr, w1h, w1l,
                                               nullptr, t, NNODE,
                                               asrc1, adst1, als, ald);

    // CSR finish
    k_scan1<<<NBLK, 1024>>>(deg, rowptr, bsum);
    k_scan2<<<1, 32>>>(bsum, boff, rowptr);
    k_scan3<<<NBLK, 1024>>>(rowptr, cursor, boff);
    k_scatter<<<(EPAD + 255) / 256, 256>>>(ei, cursor, srcs);

    // layer 1 aggregate -> h1 (bf16 split)
    k_gat_aggregate<<<NNODE, 128>>>(t, rowptr, srcs, als, ald, b1, h1h, h1l);

    // layer 2
    k_gemm_mma<128, 256, true><<<gbig, 256>>>(nullptr, h1h, h1l, w2h, w2l,
                                              nullptr, t, NNODE,
                                              asrc2, adst2, als, ald);
    k_gat_aggregate<<<NNODE, 128>>>(t, rowptr, srcs, als, ald, b2, h2h, h2l);

    // fc head
    k_gemm_mma<64, 64, true><<<gfc, 256>>>(nullptr, h2h, h2l, wfh, wfl,
                                           fcb, out, NNODE,
                                           nullptr, nullptr, nullptr, nullptr);
}

// round 8
// speedup vs baseline: 2.6024x; 1.0543x over previous
#include <cuda_runtime.h>
#include <math.h>
#include <stdint.h>

#define NNODE 50000
#define NEDGE 800000
#define EPAD  (NEDGE + NNODE)
#define FDIM  256
#define NHEAD 4
#define OUTD  64
#define NBLK  ((NNODE + 1023) / 1024)   // 49 scan blocks

// ---------------- scratch ---------------------------------------------------
__device__ __align__(128) float g_t[NNODE * FDIM];        // GEMM fp32 out
__device__ __align__(16) uint16_t g_h1h[NNODE * FDIM];    // layer-1 h, bf16 hi
__device__ __align__(16) uint16_t g_h1l[NNODE * FDIM];    // layer-1 h, bf16 lo
__device__ __align__(16) uint16_t g_h2h[NNODE * FDIM];
__device__ __align__(16) uint16_t g_h2l[NNODE * FDIM];
__device__ __align__(16) uint16_t g_w1h[FDIM * FDIM];     // W^T hi bf16 [N][K]
__device__ __align__(16) uint16_t g_w1l[FDIM * FDIM];
__device__ __align__(16) uint16_t g_w2h[FDIM * FDIM];
__device__ __align__(16) uint16_t g_w2l[FDIM * FDIM];
__device__ __align__(16) uint16_t g_wfh[OUTD * FDIM];
__device__ __align__(16) uint16_t g_wfl[OUTD * FDIM];
__device__ float g_als[NNODE * NHEAD];
__device__ float g_ald[NNODE * NHEAD];
__device__ int   g_deg[NNODE];
__device__ int   g_rowptr[NNODE + 1];
__device__ int   g_cursor[NNODE];
__device__ int   g_srcs[EPAD];
__device__ int   g_bsum[NBLK + 1];
__device__ int   g_boff[NBLK + 1];

__device__ __forceinline__ int clampi(int v, int lo, int hi) {
    return v < lo ? lo : (v > hi ? hi : v);
}
__device__ __forceinline__ uint32_t pack_bf16x2(float v0, float v1) {
    uint32_t d;
    asm("cvt.rn.bf16x2.f32 %0, %1, %2;" : "=r"(d) : "f"(v1), "f"(v0));
    return d;
}
__device__ __forceinline__ void mma_bf16(float* d, const uint32_t* a, const uint32_t* b) {
    asm volatile(
        "mma.sync.aligned.m16n8k16.row.col.f32.bf16.bf16.f32 "
        "{%0,%1,%2,%3}, {%4,%5,%6,%7}, {%8,%9}, {%0,%1,%2,%3};"
        : "+f"(d[0]), "+f"(d[1]), "+f"(d[2]), "+f"(d[3])
        : "r"(a[0]), "r"(a[1]), "r"(a[2]), "r"(a[3]), "r"(b[0]), "r"(b[1]));
}
#define LDSM_X4(r, addr)                                                     \
    asm volatile("ldmatrix.sync.aligned.m8n8.x4.shared.b16 {%0,%1,%2,%3}, [%4];" \
        : "=r"((r)[0]), "=r"((r)[1]), "=r"((r)[2]), "=r"((r)[3]) : "r"(addr))

// ---------------- CSR construction ------------------------------------------
__global__ void k_init_deg(int* deg) {
    int i = blockIdx.x * blockDim.x + threadIdx.x;
    if (i < NNODE) deg[i] = 1;
}
__global__ void k_count_deg(const int* __restrict__ ei, int* deg) {
    int e = blockIdx.x * blockDim.x + threadIdx.x;
    if (e < NEDGE) atomicAdd(&deg[clampi(ei[NEDGE + e], 0, NNODE - 1)], 1);
}
__global__ void k_scan1(const int* __restrict__ deg, int* rowptr, int* bsum) {
    int b = blockIdx.x, tid = threadIdx.x;
    int i = b * 1024 + tid;
    int v = (i < NNODE) ? deg[i] : 0;
    int lane = tid & 31, w = tid >> 5;
    int x = v;
#pragma unroll
    for (int off = 1; off < 32; off <<= 1) {
        int y = __shfl_up_sync(0xffffffffu, x, off);
        if (lane >= off) x += y;
    }
    __shared__ int ws[32];
    if (lane == 31) ws[w] = x;
    __syncthreads();
    if (w == 0) {
        int s = ws[lane];
#pragma unroll
        for (int off = 1; off < 32; off <<= 1) {
            int y = __shfl_up_sync(0xffffffffu, s, off);
            if (lane >= off) s += y;
        }
        ws[lane] = s;
    }
    __syncthreads();
    int wo = (w > 0) ? ws[w - 1] : 0;
    int incl = x + wo;
    if (i < NNODE) rowptr[i] = incl - v;
    if (tid == 1023) bsum[b] = incl;
}
__global__ void k_scan2(const int* __restrict__ bsum, int* boff, int* rowptr) {
    if (threadIdx.x == 0) {
        int s = 0;
        for (int b = 0; b < NBLK; b++) { boff[b] = s; s += bsum[b]; }
        rowptr[NNODE] = s;
    }
}
__global__ void k_scan3(int* rowptr, int* cursor, const int* __restrict__ boff) {
    int i = blockIdx.x * blockDim.x + threadIdx.x;
    if (i < NNODE) {
        int r = rowptr[i] + boff[i >> 10];
        rowptr[i] = r;
        cursor[i] = r;
    }
}
__global__ void k_scatter(const int* __restrict__ ei, int* cursor, int* srcs) {
    int e = blockIdx.x * blockDim.x + threadIdx.x;
    if (e < NEDGE) {
        int s = clampi(ei[e], 0, NNODE - 1);
        int d = clampi(ei[NEDGE + e], 0, NNODE - 1);
        int pos = atomicAdd(&cursor[d], 1);
        if (pos >= 0 && pos < EPAD) srcs[pos] = s;
    } else if (e < EPAD) {
        int i = e - NEDGE;
        int pos = atomicAdd(&cursor[i], 1);
        if (pos >= 0 && pos < EPAD) srcs[pos] = i;
    }
}

// ---------------- weight split/transpose: W[K][N] -> hi/lo bf16 [N][K] ------
__global__ void k_split_w(const float* __restrict__ W, uint16_t* __restrict__ WH,
                          uint16_t* __restrict__ WL, int K, int N) {
    int i = blockIdx.x * blockDim.x + threadIdx.x;
    if (i < K * N) {
        int k = i / N, n = i % N;
        float v = W[i];
        uint32_t hw = pack_bf16x2(v, 0.f);
        float hf = __uint_as_float(hw << 16);
        uint32_t lw = pack_bf16x2(v - hf, 0.f);
        WH[n * K + k] = (uint16_t)(hw & 0xffffu);
        WL[n * K + k] = (uint16_t)(lw & 0xffffu);
    }
}

// ---------------- bf16-split tensor-core GEMM + fused logits ----------------
// C[M,NOUT] = A[M,256] @ B (pre-split bf16 hi/lo, [NOUT][256] K-major) (+bias)
// Fragments via ldmatrix.x4; RS=40 pad tiles all 32 banks conflict-free.
template<int BN, int NOUT, bool PRESPLIT>
__global__ void __launch_bounds__(256, 2)
k_gemm_mma(const float* __restrict__ A,
           const uint16_t* __restrict__ AH, const uint16_t* __restrict__ AL,
           const uint16_t* __restrict__ BH, const uint16_t* __restrict__ BL,
           const float* __restrict__ bias, float* __restrict__ C, int M,
           const float* __restrict__ a_src, const float* __restrict__ a_dst,
           float* __restrict__ als_out, float* __restrict__ ald_out) {
    constexpr int RS = 40;
    constexpr int WN = BN / 2;
    constexpr int NT = WN / 8;
    constexpr int NP = NT / 2;               // ldmatrix nt-pairs
    constexpr int A_F4 = 4;
    constexpr int A_U4 = 2;
    constexpr int B_U4 = BN * 4 / 256;

    __shared__ __align__(16) uint16_t sAh[128 * RS];
    __shared__ __align__(16) uint16_t sAl[128 * RS];
    __shared__ __align__(16) uint16_t sBh[BN * RS];
    __shared__ __align__(16) uint16_t sBl[BN * RS];

    const int tid  = threadIdx.x;
    const int wid  = tid >> 5, lane = tid & 31;
    const int wm   = wid & 3, wn = wid >> 2;
    const int g    = lane >> 2, tq = lane & 3;
    const int brow = blockIdx.x * 128;
    const int bcol = blockIdx.y * BN;

    float acc[2][NT][4];
#pragma unroll
    for (int mt = 0; mt < 2; mt++)
#pragma unroll
        for (int nt = 0; nt < NT; nt++)
#pragma unroll
            for (int r = 0; r < 4; r++) acc[mt][nt][r] = 0.f;

    // ldmatrix per-lane source addresses (byte offsets within smem tiles)
    const int lane8 = lane & 7, lh = (lane >> 3) & 1, lq = lane >> 4;
    const uint32_t sAh_b = (uint32_t)__cvta_generic_to_shared(sAh);
    const uint32_t sAl_b = (uint32_t)__cvta_generic_to_shared(sAl);
    const uint32_t sBh_b = (uint32_t)__cvta_generic_to_shared(sBh);
    const uint32_t sBl_b = (uint32_t)__cvta_generic_to_shared(sBl);
    uint32_t aHiA[2], aLoA[2], bHiA[NP], bLoA[NP];
#pragma unroll
    for (int mt = 0; mt < 2; mt++) {
        int ar = wm * 32 + mt * 16 + lane8 + lh * 8;
        int ac = lq * 8;
        aHiA[mt] = sAh_b + (ar * RS + ac) * 2;
        aLoA[mt] = sAl_b + (ar * RS + ac) * 2;
    }
#pragma unroll
    for (int p = 0; p < NP; p++) {
        int br = wn * WN + p * 16 + lane8 + lq * 8;
        int bc = lh * 8;
        bHiA[p] = sBh_b + (br * RS + bc) * 2;
        bLoA[p] = sBl_b + (br * RS + bc) * 2;
    }

    float4 aS[A_F4];
    uint4  aSh[A_U4], aSl[A_U4];
    uint4  bSh[B_U4], bSl[B_U4];

    auto load_regs = [&](int k0) {
        if (PRESPLIT) {
#pragma unroll
            for (int u = 0; u < A_U4; u++) {
                int q = tid + u * 256;
                int row = q >> 2, c8 = q & 3;
                int gr = brow + row;
                if (gr < M) {
                    size_t gi = (size_t)gr * 256 + k0 + c8 * 8;
                    aSh[u] = *reinterpret_cast<const uint4*>(&AH[gi]);
                    aSl[u] = *reinterpret_cast<const uint4*>(&AL[gi]);
                } else {
                    aSh[u] = make_uint4(0, 0, 0, 0);
                    aSl[u] = make_uint4(0, 0, 0, 0);
                }
            }
        } else {
#pragma unroll
            for (int u = 0; u < A_F4; u++) {
                int q = tid + u * 256;
                int row = q >> 3, f4 = q & 7;
                int gr = brow + row;
                aS[u] = make_float4(0.f, 0.f, 0.f, 0.f);
                if (gr < M) aS[u] = *reinterpret_cast<const float4*>(&A[(size_t)gr * 256 + k0 + f4 * 4]);
            }
        }
#pragma unroll
        for (int u = 0; u < B_U4; u++) {
            int q = tid + u * 256;
            int row = q >> 2, c8 = q & 3;
            size_t gi = (size_t)(bcol + row) * 256 + k0 + c8 * 8;
            bSh[u] = *reinterpret_cast<const uint4*>(&BH[gi]);
            bSl[u] = *reinterpret_cast<const uint4*>(&BL[gi]);
        }
    };
    auto split_store = [](uint16_t* hb, uint16_t* lb, int idx, float v0, float v1) {
        uint32_t hw = pack_bf16x2(v0, v1);
        float f0 = __uint_as_float(hw << 16);
        float f1 = __uint_as_float(hw & 0xffff0000u);
        uint32_t lw = pack_bf16x2(v0 - f0, v1 - f1);
        *reinterpret_cast<uint32_t*>(hb + idx) = hw;
        *reinterpret_cast<uint32_t*>(lb + idx) = lw;
    };
    auto store_smem = [&]() {
        if (PRESPLIT) {
#pragma unroll
            for (int u = 0; u < A_U4; u++) {
                int q = tid + u * 256;
                int row = q >> 2, c8 = q & 3;
                int idx = row * RS + c8 * 8;
                *reinterpret_cast<uint4*>(&sAh[idx]) = aSh[u];
                *reinterpret_cast<uint4*>(&sAl[idx]) = aSl[u];
            }
        } else {
#pragma unroll
            for (int u = 0; u < A_F4; u++) {
                int q = tid + u * 256;
                int row = q >> 3, f4 = q & 7;
                int idx = row * RS + f4 * 4;
                split_store(sAh, sAl, idx,     aS[u].x, aS[u].y);
                split_store(sAh, sAl, idx + 2, aS[u].z, aS[u].w);
            }
        }
#pragma unroll
        for (int u = 0; u < B_U4; u++) {
            int q = tid + u * 256;
            int row = q >> 2, c8 = q & 3;
            int idx = row * RS + c8 * 8;
            *reinterpret_cast<uint4*>(&sBh[idx]) = bSh[u];
            *reinterpret_cast<uint4*>(&sBl[idx]) = bSl[u];
        }
    };

    load_regs(0);
    store_smem();
    __syncthreads();

    for (int t = 0; t < 8; t++) {
        if (t + 1 < 8) load_regs((t + 1) * 32);

#pragma unroll
        for (int ks = 0; ks < 2; ks++) {
            const uint32_t kb = ks * 32;   // byte offset (16 halves)
            uint32_t ah[2][4], al[2][4];
            LDSM_X4(ah[0], aHiA[0] + kb);
            LDSM_X4(ah[1], aHiA[1] + kb);
            LDSM_X4(al[0], aLoA[0] + kb);
            LDSM_X4(al[1], aLoA[1] + kb);
#pragma unroll
            for (int p = 0; p < NP; p++) {
                uint32_t bh[4], bl[4];
                LDSM_X4(bh, bHiA[p] + kb);
                LDSM_X4(bl, bLoA[p] + kb);
#pragma unroll
                for (int mt = 0; mt < 2; mt++) {
                    mma_bf16(acc[mt][2 * p],     ah[mt], bh);
                    mma_bf16(acc[mt][2 * p],     ah[mt], bl);
                    mma_bf16(acc[mt][2 * p],     al[mt], bh);
                    mma_bf16(acc[mt][2 * p + 1], ah[mt], bh + 2);
                    mma_bf16(acc[mt][2 * p + 1], ah[mt], bl + 2);
                    mma_bf16(acc[mt][2 * p + 1], al[mt], bh + 2);
                }
            }
        }

        if (t + 1 < 8) {
            __syncthreads();
            store_smem();
            __syncthreads();
        }
    }

    // epilogue: C stores (fragment-direct float2)
#pragma unroll
    for (int mt = 0; mt < 2; mt++) {
        int r0 = brow + wm * 32 + mt * 16 + g;
        int r1 = r0 + 8;
#pragma unroll
        for (int nt = 0; nt < NT; nt++) {
            int col = bcol + wn * WN + nt * 8 + tq * 2;
            float b0 = 0.f, b1 = 0.f;
            if (bias) { b0 = bias[col]; b1 = bias[col + 1]; }
            if (r0 < M)
                *reinterpret_cast<float2*>(&C[(size_t)r0 * NOUT + col]) =
                    make_float2(acc[mt][nt][0] + b0, acc[mt][nt][1] + b1);
            if (r1 < M)
                *reinterpret_cast<float2*>(&C[(size_t)r1 * NOUT + col]) =
                    make_float2(acc[mt][nt][2] + b0, acc[mt][nt][3] + b1);
        }
    }

    // fused attention logits (BN==128): head = blockIdx.y*2 + wn
    if (als_out) {
        int head = blockIdx.y * 2 + wn;
#pragma unroll
        for (int mt = 0; mt < 2; mt++) {
#pragma unroll
            for (int half = 0; half < 2; half++) {
                float ps = 0.f, pd = 0.f;
#pragma unroll
                for (int nt = 0; nt < NT; nt++) {
                    int col = bcol + wn * WN + nt * 8 + tq * 2;
                    float a0 = acc[mt][nt][half * 2 + 0];
                    float a1 = acc[mt][nt][half * 2 + 1];
                    ps += a0 * a_src[col] + a1 * a_src[col + 1];
                    pd += a0 * a_dst[col] + a1 * a_dst[col + 1];
                }
                ps += __shfl_xor_sync(0xffffffffu, ps, 1);
                pd += __shfl_xor_sync(0xffffffffu, pd, 1);
                ps += __shfl_xor_sync(0xffffffffu, ps, 2);
                pd += __shfl_xor_sync(0xffffffffu, pd, 2);
                int row = brow + wm * 32 + mt * 16 + g + half * 8;
                if (tq == 0 && row < M) {
                    als_out[row * NHEAD + head] = ps;
                    ald_out[row * NHEAD + head] = pd;
                }
            }
        }
    }
}

// ---------------- warp-synchronous aggregation (no smem, no block sync) -----
// 128 threads/node; warp w owns head w (channels w*64..w*64+63 as 32 float2).
__global__ void __launch_bounds__(128)
k_gat_aggregate(const float* __restrict__ hsrc,
                const int* __restrict__ rowptr,
                const int* __restrict__ srcs,
                const float* __restrict__ als,
                const float* __restrict__ ald,
                const float* __restrict__ bias,
                uint16_t* __restrict__ outh, uint16_t* __restrict__ outl) {
    int n = blockIdx.x;
    int w = threadIdx.x >> 5;    // head == warp
    int lane = threadIdx.x & 31;

    int p0  = rowptr[n];
    int deg = rowptr[n + 1] - p0;

    float aldv = __ldg(&ald[n * NHEAD + w]);
    float accx = 0.f, accy = 0.f, dsum = 0.f;

    const float2* h2 = reinterpret_cast<const float2*>(hsrc);

    for (int base = 0; base < deg; base += 32) {
        int j = base + lane;
        int s = 0;
        float wt = 0.f;
        if (j < deg) {
            s = srcs[p0 + j];
            float e = als[s * NHEAD + w] + aldv;
            e = (e > 0.f) ? e : 0.2f * e;
            wt = __expf(e);
            dsum += wt;
        }
        int lim = min(32, deg - base);
#pragma unroll 4
        for (int j2 = 0; j2 < lim; j2++) {
            int   ss = __shfl_sync(0xffffffffu, s,  j2);
            float ww = __shfl_sync(0xffffffffu, wt, j2);
            float2 v = h2[(size_t)ss * 128 + w * 32 + lane];
            accx += ww * v.x;
            accy += ww * v.y;
        }
    }

#pragma unroll
    for (int off = 16; off >= 1; off >>= 1)
        dsum += __shfl_xor_sync(0xffffffffu, dsum, off);

    float inv = 1.f / dsum;
    int c2 = w * 32 + lane;
    float o0 = accx * inv + bias[2 * c2];
    float o1 = accy * inv + bias[2 * c2 + 1];
    o0 = (o0 > 0.f) ? o0 : expm1f(o0);
    o1 = (o1 > 0.f) ? o1 : expm1f(o1);

    uint32_t hw = pack_bf16x2(o0, o1);
    float f0 = __uint_as_float(hw << 16);
    float f1 = __uint_as_float(hw & 0xffff0000u);
    uint32_t lw = pack_bf16x2(o0 - f0, o1 - f1);
    reinterpret_cast<uint32_t*>(outh)[(size_t)n * 128 + c2] = hw;
    reinterpret_cast<uint32_t*>(outl)[(size_t)n * 128 + c2] = lw;
}

// ---------------- launch ----------------------------------------------------
extern "C" void kernel_launch(void* const* d_in, const int* in_sizes, int n_in,
                              void* d_out, int out_size) {
    const float* x     = (const float*)d_in[0];
    const int*   ei    = (const int*)d_in[1];   // int32 (JAX x64 disabled)
    const float* W1    = (const float*)d_in[3];
    const float* asrc1 = (const float*)d_in[4];
    const float* adst1 = (const float*)d_in[5];
    const float* b1    = (const float*)d_in[6];
    const float* W2    = (const float*)d_in[7];
    const float* asrc2 = (const float*)d_in[8];
    const float* adst2 = (const float*)d_in[9];
    const float* b2    = (const float*)d_in[10];
    const float* fcW   = (const float*)d_in[11];
    const float* fcb   = (const float*)d_in[12];
    float* out = (float*)d_out;

    float *t, *als, *ald;
    uint16_t *h1h, *h1l, *h2h, *h2l;
    uint16_t *w1h, *w1l, *w2h, *w2l, *wfh, *wfl;
    int *deg, *rowptr, *cursor, *srcs, *bsum, *boff;
    cudaGetSymbolAddress((void**)&t, g_t);
    cudaGetSymbolAddress((void**)&h1h, g_h1h);
    cudaGetSymbolAddress((void**)&h1l, g_h1l);
    cudaGetSymbolAddress((void**)&h2h, g_h2h);
    cudaGetSymbolAddress((void**)&h2l, g_h2l);
    cudaGetSymbolAddress((void**)&als, g_als);
    cudaGetSymbolAddress((void**)&ald, g_ald);
    cudaGetSymbolAddress((void**)&w1h, g_w1h);
    cudaGetSymbolAddress((void**)&w1l, g_w1l);
    cudaGetSymbolAddress((void**)&w2h, g_w2h);
    cudaGetSymbolAddress((void**)&w2l, g_w2l);
    cudaGetSymbolAddress((void**)&wfh, g_wfh);
    cudaGetSymbolAddress((void**)&wfl, g_wfl);
    cudaGetSymbolAddress((void**)&deg, g_deg);
    cudaGetSymbolAddress((void**)&rowptr, g_rowptr);
    cudaGetSymbolAddress((void**)&cursor, g_cursor);
    cudaGetSymbolAddress((void**)&srcs, g_srcs);
    cudaGetSymbolAddress((void**)&bsum, g_bsum);
    cudaGetSymbolAddress((void**)&boff, g_boff);

    const int NTILE = (NNODE + 127) / 128;   // 391
    dim3 gbig(NTILE, 2);
    dim3 gfc(NTILE, 1);

    k_split_w<<<(FDIM * FDIM + 255) / 256, 256>>>(W1, w1h, w1l, FDIM, FDIM);
    k_split_w<<<(FDIM * FDIM + 255) / 256, 256>>>(W2, w2h, w2l, FDIM, FDIM);
    k_split_w<<<(FDIM * OUTD + 255) / 256, 256>>>(fcW, wfh, wfl, FDIM, OUTD);
    k_init_deg<<<(NNODE + 255) / 256, 256>>>(deg);
    k_count_deg<<<(NEDGE + 255) / 256, 256>>>(ei, deg);

    // layer-1 GEMM (+fused logits)
    k_gemm_mma<128, 256, false><<<gbig, 256>>>(x, nullptr, nullptr, w1h, w1l,
                                               nullptr, t, NNODE,
                                               asrc1, adst1, als, ald);

    // CSR finish
    k_scan1<<<NBLK, 1024>>>(deg, rowptr, bsum);
    k_scan2<<<1, 32>>>(bsum, boff, rowptr);
    k_scan3<<<NBLK, 1024>>>(rowptr, cursor, boff);
    k_scatter<<<(EPAD + 255) / 256, 256>>>(ei, cursor, srcs);

    // layer 1 aggregate -> h1 (bf16 split)
    k_gat_aggregate<<<NNODE, 128>>>(t, rowptr, srcs, als, ald, b1, h1h, h1l);

    // layer 2
    k_gemm_mma<128, 256, true><<<gbig, 256>>>(nullptr, h1h, h1l, w2h, w2l,
                                              nullptr, t, NNODE,
                                              asrc2, adst2, als, ald);
    k_gat_aggregate<<<NNODE, 128>>>(t, rowptr, srcs, als, ald, b2, h2h, h2l);

    // fc head
    k_gemm_mma<64, 64, true><<<gfc, 256>>>(nullptr, h2h, h2l, wfh, wfl,
                                           fcb, out, NNODE,
                                           nullptr, nullptr, nullptr, nullptr);
}

// round 9
// speedup vs baseline: 2.7320x; 1.0498x over previous
#include <cuda_runtime.h>
#include <math.h>
#include <stdint.h>

#define NNODE 50000
#define NEDGE 800000
#define EPAD  (NEDGE + NNODE)
#define FDIM  256
#define NHEAD 4
#define OUTD  64
#define NBLK  ((NNODE + 1023) / 1024)   // 49 scan blocks

// ---------------- scratch ---------------------------------------------------
__device__ __align__(128) float g_t[NNODE * FDIM];        // GEMM fp32 out
__device__ __align__(16) uint16_t g_h1h[NNODE * FDIM];    // layer-1 h, bf16 hi
__device__ __align__(16) uint16_t g_h1l[NNODE * FDIM];    // layer-1 h, bf16 lo
__device__ __align__(16) uint16_t g_h2h[NNODE * FDIM];
__device__ __align__(16) uint16_t g_h2l[NNODE * FDIM];
__device__ __align__(16) uint16_t g_w1h[FDIM * FDIM];     // W^T hi bf16 [N][K]
__device__ __align__(16) uint16_t g_w1l[FDIM * FDIM];
__device__ __align__(16) uint16_t g_w2h[FDIM * FDIM];
__device__ __align__(16) uint16_t g_w2l[FDIM * FDIM];
__device__ __align__(16) uint16_t g_wfh[OUTD * FDIM];
__device__ __align__(16) uint16_t g_wfl[OUTD * FDIM];
__device__ float g_als[NNODE * NHEAD];
__device__ float g_ald[NNODE * NHEAD];
__device__ int   g_deg[NNODE];
__device__ int   g_rowptr[NNODE + 1];
__device__ int   g_cursor[NNODE];
__device__ int   g_srcs[EPAD];
__device__ int   g_bsum[NBLK + 1];
__device__ int   g_boff[NBLK + 1];

__device__ __forceinline__ int clampi(int v, int lo, int hi) {
    return v < lo ? lo : (v > hi ? hi : v);
}
__device__ __forceinline__ uint32_t pack_bf16x2(float v0, float v1) {
    uint32_t d;
    asm("cvt.rn.bf16x2.f32 %0, %1, %2;" : "=r"(d) : "f"(v1), "f"(v0));
    return d;
}
__device__ __forceinline__ void mma_bf16(float* d, const uint32_t* a, const uint32_t* b) {
    asm volatile(
        "mma.sync.aligned.m16n8k16.row.col.f32.bf16.bf16.f32 "
        "{%0,%1,%2,%3}, {%4,%5,%6,%7}, {%8,%9}, {%0,%1,%2,%3};"
        : "+f"(d[0]), "+f"(d[1]), "+f"(d[2]), "+f"(d[3])
        : "r"(a[0]), "r"(a[1]), "r"(a[2]), "r"(a[3]), "r"(b[0]), "r"(b[1]));
}
#define LDSM_X4(r, addr)                                                     \
    asm volatile("ldmatrix.sync.aligned.m8n8.x4.shared.b16 {%0,%1,%2,%3}, [%4];" \
        : "=r"((r)[0]), "=r"((r)[1]), "=r"((r)[2]), "=r"((r)[3]) : "r"(addr))

// ---------------- CSR construction ------------------------------------------
__global__ void k_count_deg(const int* __restrict__ ei, int* deg) {
    int e = blockIdx.x * blockDim.x + threadIdx.x;
    if (e < NEDGE) atomicAdd(&deg[clampi(ei[NEDGE + e], 0, NNODE - 1)], 1);
}
// deg holds edge-only counts; +1 self loop folded into the scan
__global__ void k_scan1(const int* __restrict__ deg, int* rowptr, int* bsum) {
    int b = blockIdx.x, tid = threadIdx.x;
    int i = b * 1024 + tid;
    int v = (i < NNODE) ? (deg[i] + 1) : 0;
    int lane = tid & 31, w = tid >> 5;
    int x = v;
#pragma unroll
    for (int off = 1; off < 32; off <<= 1) {
        int y = __shfl_up_sync(0xffffffffu, x, off);
        if (lane >= off) x += y;
    }
    __shared__ int ws[32];
    if (lane == 31) ws[w] = x;
    __syncthreads();
    if (w == 0) {
        int s = ws[lane];
#pragma unroll
        for (int off = 1; off < 32; off <<= 1) {
            int y = __shfl_up_sync(0xffffffffu, s, off);
            if (lane >= off) s += y;
        }
        ws[lane] = s;
    }
    __syncthreads();
    int wo = (w > 0) ? ws[w - 1] : 0;
    int incl = x + wo;
    if (i < NNODE) rowptr[i] = incl - v;
    if (tid == 1023) bsum[b] = incl;
}
__global__ void k_scan2(const int* __restrict__ bsum, int* boff, int* rowptr) {
    if (threadIdx.x == 0) {
        int s = 0;
        for (int b = 0; b < NBLK; b++) { boff[b] = s; s += bsum[b]; }
        rowptr[NNODE] = s;
    }
}
__global__ void k_scan3(int* rowptr, int* cursor, const int* __restrict__ boff) {
    int i = blockIdx.x * blockDim.x + threadIdx.x;
    if (i < NNODE) {
        int r = rowptr[i] + boff[i >> 10];
        rowptr[i] = r;
        cursor[i] = r;
    }
}
__global__ void k_scatter(const int* __restrict__ ei, int* cursor, int* srcs) {
    int e = blockIdx.x * blockDim.x + threadIdx.x;
    if (e < NEDGE) {
        int s = clampi(ei[e], 0, NNODE - 1);
        int d = clampi(ei[NEDGE + e], 0, NNODE - 1);
        int pos = atomicAdd(&cursor[d], 1);
        if (pos >= 0 && pos < EPAD) srcs[pos] = s;
    } else if (e < EPAD) {
        int i = e - NEDGE;
        int pos = atomicAdd(&cursor[i], 1);
        if (pos >= 0 && pos < EPAD) srcs[pos] = i;
    }
}

// ---------------- weight split/transpose: W[K][N] -> hi/lo bf16 [N][K] ------
__global__ void k_split_w(const float* __restrict__ W, uint16_t* __restrict__ WH,
                          uint16_t* __restrict__ WL, int K, int N) {
    int i = blockIdx.x * blockDim.x + threadIdx.x;
    if (i < K * N) {
        int k = i / N, n = i % N;
        float v = W[i];
        uint32_t hw = pack_bf16x2(v, 0.f);
        float hf = __uint_as_float(hw << 16);
        uint32_t lw = pack_bf16x2(v - hf, 0.f);
        WH[n * K + k] = (uint16_t)(hw & 0xffffu);
        WL[n * K + k] = (uint16_t)(lw & 0xffffu);
    }
}

// ---------------- bf16-split tensor-core GEMM + fused logits ----------------
template<int BN, int NOUT, bool PRESPLIT>
__global__ void __launch_bounds__(256, 2)
k_gemm_mma(const float* __restrict__ A,
           const uint16_t* __restrict__ AH, const uint16_t* __restrict__ AL,
           const uint16_t* __restrict__ BH, const uint16_t* __restrict__ BL,
           const float* __restrict__ bias, float* __restrict__ C, int M,
           const float* __restrict__ a_src, const float* __restrict__ a_dst,
           float* __restrict__ als_out, float* __restrict__ ald_out) {
    constexpr int RS = 40;
    constexpr int WN = BN / 2;
    constexpr int NT = WN / 8;
    constexpr int NP = NT / 2;               // ldmatrix nt-pairs
    constexpr int A_F4 = 4;
    constexpr int A_U4 = 2;
    constexpr int B_U4 = BN * 4 / 256;

    __shared__ __align__(16) uint16_t sAh[128 * RS];
    __shared__ __align__(16) uint16_t sAl[128 * RS];
    __shared__ __align__(16) uint16_t sBh[BN * RS];
    __shared__ __align__(16) uint16_t sBl[BN * RS];

    const int tid  = threadIdx.x;
    const int wid  = tid >> 5, lane = tid & 31;
    const int wm   = wid & 3, wn = wid >> 2;
    const int g    = lane >> 2, tq = lane & 3;
    const int brow = blockIdx.x * 128;
    const int bcol = blockIdx.y * BN;

    float acc[2][NT][4];
#pragma unroll
    for (int mt = 0; mt < 2; mt++)
#pragma unroll
        for (int nt = 0; nt < NT; nt++)
#pragma unroll
            for (int r = 0; r < 4; r++) acc[mt][nt][r] = 0.f;

    const int lane8 = lane & 7, lh = (lane >> 3) & 1, lq = lane >> 4;
    const uint32_t sAh_b = (uint32_t)__cvta_generic_to_shared(sAh);
    const uint32_t sAl_b = (uint32_t)__cvta_generic_to_shared(sAl);
    const uint32_t sBh_b = (uint32_t)__cvta_generic_to_shared(sBh);
    const uint32_t sBl_b = (uint32_t)__cvta_generic_to_shared(sBl);
    uint32_t aHiA[2], aLoA[2], bHiA[NP], bLoA[NP];
#pragma unroll
    for (int mt = 0; mt < 2; mt++) {
        int ar = wm * 32 + mt * 16 + lane8 + lh * 8;
        int ac = lq * 8;
        aHiA[mt] = sAh_b + (ar * RS + ac) * 2;
        aLoA[mt] = sAl_b + (ar * RS + ac) * 2;
    }
#pragma unroll
    for (int p = 0; p < NP; p++) {
        int br = wn * WN + p * 16 + lane8 + lq * 8;
        int bc = lh * 8;
        bHiA[p] = sBh_b + (br * RS + bc) * 2;
        bLoA[p] = sBl_b + (br * RS + bc) * 2;
    }

    float4 aS[A_F4];
    uint4  aSh[A_U4], aSl[A_U4];
    uint4  bSh[B_U4], bSl[B_U4];

    auto load_regs = [&](int k0) {
        if (PRESPLIT) {
#pragma unroll
            for (int u = 0; u < A_U4; u++) {
                int q = tid + u * 256;
                int row = q >> 2, c8 = q & 3;
                int gr = brow + row;
                if (gr < M) {
                    size_t gi = (size_t)gr * 256 + k0 + c8 * 8;
                    aSh[u] = *reinterpret_cast<const uint4*>(&AH[gi]);
                    aSl[u] = *reinterpret_cast<const uint4*>(&AL[gi]);
                } else {
                    aSh[u] = make_uint4(0, 0, 0, 0);
                    aSl[u] = make_uint4(0, 0, 0, 0);
                }
            }
        } else {
#pragma unroll
            for (int u = 0; u < A_F4; u++) {
                int q = tid + u * 256;
                int row = q >> 3, f4 = q & 7;
                int gr = brow + row;
                aS[u] = make_float4(0.f, 0.f, 0.f, 0.f);
                if (gr < M) aS[u] = *reinterpret_cast<const float4*>(&A[(size_t)gr * 256 + k0 + f4 * 4]);
            }
        }
#pragma unroll
        for (int u = 0; u < B_U4; u++) {
            int q = tid + u * 256;
            int row = q >> 2, c8 = q & 3;
            size_t gi = (size_t)(bcol + row) * 256 + k0 + c8 * 8;
            bSh[u] = *reinterpret_cast<const uint4*>(&BH[gi]);
            bSl[u] = *reinterpret_cast<const uint4*>(&BL[gi]);
        }
    };
    auto split_store = [](uint16_t* hb, uint16_t* lb, int idx, float v0, float v1) {
        uint32_t hw = pack_bf16x2(v0, v1);
        float f0 = __uint_as_float(hw << 16);
        float f1 = __uint_as_float(hw & 0xffff0000u);
        uint32_t lw = pack_bf16x2(v0 - f0, v1 - f1);
        *reinterpret_cast<uint32_t*>(hb + idx) = hw;
        *reinterpret_cast<uint32_t*>(lb + idx) = lw;
    };
    auto store_smem = [&]() {
        if (PRESPLIT) {
#pragma unroll
            for (int u = 0; u < A_U4; u++) {
                int q = tid + u * 256;
                int row = q >> 2, c8 = q & 3;
                int idx = row * RS + c8 * 8;
                *reinterpret_cast<uint4*>(&sAh[idx]) = aSh[u];
                *reinterpret_cast<uint4*>(&sAl[idx]) = aSl[u];
            }
        } else {
#pragma unroll
            for (int u = 0; u < A_F4; u++) {
                int q = tid + u * 256;
                int row = q >> 3, f4 = q & 7;
                int idx = row * RS + f4 * 4;
                split_store(sAh, sAl, idx,     aS[u].x, aS[u].y);
                split_store(sAh, sAl, idx + 2, aS[u].z, aS[u].w);
            }
        }
#pragma unroll
        for (int u = 0; u < B_U4; u++) {
            int q = tid + u * 256;
            int row = q >> 2, c8 = q & 3;
            int idx = row * RS + c8 * 8;
            *reinterpret_cast<uint4*>(&sBh[idx]) = bSh[u];
            *reinterpret_cast<uint4*>(&sBl[idx]) = bSl[u];
        }
    };

    load_regs(0);
    store_smem();
    __syncthreads();

    for (int t = 0; t < 8; t++) {
        if (t + 1 < 8) load_regs((t + 1) * 32);

#pragma unroll
        for (int ks = 0; ks < 2; ks++) {
            const uint32_t kb = ks * 32;   // byte offset (16 halves)
            uint32_t ah[2][4], al[2][4];
            LDSM_X4(ah[0], aHiA[0] + kb);
            LDSM_X4(ah[1], aHiA[1] + kb);
            LDSM_X4(al[0], aLoA[0] + kb);
            LDSM_X4(al[1], aLoA[1] + kb);
#pragma unroll
            for (int p = 0; p < NP; p++) {
                uint32_t bh[4], bl[4];
                LDSM_X4(bh, bHiA[p] + kb);
                LDSM_X4(bl, bLoA[p] + kb);
#pragma unroll
                for (int mt = 0; mt < 2; mt++) {
                    mma_bf16(acc[mt][2 * p],     ah[mt], bh);
                    mma_bf16(acc[mt][2 * p],     ah[mt], bl);
                    mma_bf16(acc[mt][2 * p],     al[mt], bh);
                    mma_bf16(acc[mt][2 * p + 1], ah[mt], bh + 2);
                    mma_bf16(acc[mt][2 * p + 1], ah[mt], bl + 2);
                    mma_bf16(acc[mt][2 * p + 1], al[mt], bh + 2);
                }
            }
        }

        if (t + 1 < 8) {
            __syncthreads();
            store_smem();
            __syncthreads();
        }
    }

#pragma unroll
    for (int mt = 0; mt < 2; mt++) {
        int r0 = brow + wm * 32 + mt * 16 + g;
        int r1 = r0 + 8;
#pragma unroll
        for (int nt = 0; nt < NT; nt++) {
            int col = bcol + wn * WN + nt * 8 + tq * 2;
            float b0 = 0.f, b1 = 0.f;
            if (bias) { b0 = bias[col]; b1 = bias[col + 1]; }
            if (r0 < M)
                *reinterpret_cast<float2*>(&C[(size_t)r0 * NOUT + col]) =
                    make_float2(acc[mt][nt][0] + b0, acc[mt][nt][1] + b1);
            if (r1 < M)
                *reinterpret_cast<float2*>(&C[(size_t)r1 * NOUT + col]) =
                    make_float2(acc[mt][nt][2] + b0, acc[mt][nt][3] + b1);
        }
    }

    if (als_out) {
        int head = blockIdx.y * 2 + wn;
#pragma unroll
        for (int mt = 0; mt < 2; mt++) {
#pragma unroll
            for (int half = 0; half < 2; half++) {
                float ps = 0.f, pd = 0.f;
#pragma unroll
                for (int nt = 0; nt < NT; nt++) {
                    int col = bcol + wn * WN + nt * 8 + tq * 2;
                    float a0 = acc[mt][nt][half * 2 + 0];
                    float a1 = acc[mt][nt][half * 2 + 1];
                    ps += a0 * a_src[col] + a1 * a_src[col + 1];
                    pd += a0 * a_dst[col] + a1 * a_dst[col + 1];
                }
                ps += __shfl_xor_sync(0xffffffffu, ps, 1);
                pd += __shfl_xor_sync(0xffffffffu, pd, 1);
                ps += __shfl_xor_sync(0xffffffffu, ps, 2);
                pd += __shfl_xor_sync(0xffffffffu, pd, 2);
                int row = brow + wm * 32 + mt * 16 + g + half * 8;
                if (tq == 0 && row < M) {
                    als_out[row * NHEAD + head] = ps;
                    ald_out[row * NHEAD + head] = pd;
                }
            }
        }
    }
}

// ---------------- warp-synchronous aggregation ------------------------------
__global__ void __launch_bounds__(128)
k_gat_aggregate(const float* __restrict__ hsrc,
                const int* __restrict__ rowptr,
                const int* __restrict__ srcs,
                const float* __restrict__ als,
                const float* __restrict__ ald,
                const float* __restrict__ bias,
                uint16_t* __restrict__ outh, uint16_t* __restrict__ outl) {
    int n = blockIdx.x;
    int w = threadIdx.x >> 5;    // head == warp
    int lane = threadIdx.x & 31;

    int p0  = rowptr[n];
    int deg = rowptr[n + 1] - p0;

    float aldv = __ldg(&ald[n * NHEAD + w]);
    float accx = 0.f, accy = 0.f, dsum = 0.f;

    const float2* h2 = reinterpret_cast<const float2*>(hsrc);

    for (int base = 0; base < deg; base += 32) {
        int j = base + lane;
        int s = 0;
        float wt = 0.f;
        if (j < deg) {
            s = srcs[p0 + j];
            float e = als[s * NHEAD + w] + aldv;
            e = (e > 0.f) ? e : 0.2f * e;
            wt = __expf(e);
            dsum += wt;
        }
        int lim = min(32, deg - base);
#pragma unroll 4
        for (int j2 = 0; j2 < lim; j2++) {
            int   ss = __shfl_sync(0xffffffffu, s,  j2);
            float ww = __shfl_sync(0xffffffffu, wt, j2);
            float2 v = h2[(size_t)ss * 128 + w * 32 + lane];
            accx += ww * v.x;
            accy += ww * v.y;
        }
    }

#pragma unroll
    for (int off = 16; off >= 1; off >>= 1)
        dsum += __shfl_xor_sync(0xffffffffu, dsum, off);

    float inv = 1.f / dsum;
    int c2 = w * 32 + lane;
    float o0 = accx * inv + bias[2 * c2];
    float o1 = accy * inv + bias[2 * c2 + 1];
    o0 = (o0 > 0.f) ? o0 : expm1f(o0);
    o1 = (o1 > 0.f) ? o1 : expm1f(o1);

    uint32_t hw = pack_bf16x2(o0, o1);
    float f0 = __uint_as_float(hw << 16);
    float f1 = __uint_as_float(hw & 0xffff0000u);
    uint32_t lw = pack_bf16x2(o0 - f0, o1 - f1);
    reinterpret_cast<uint32_t*>(outh)[(size_t)n * 128 + c2] = hw;
    reinterpret_cast<uint32_t*>(outl)[(size_t)n * 128 + c2] = lw;
}

// ---------------- launch ----------------------------------------------------
extern "C" void kernel_launch(void* const* d_in, const int* in_sizes, int n_in,
                              void* d_out, int out_size) {
    const float* x     = (const float*)d_in[0];
    const int*   ei    = (const int*)d_in[1];   // int32 (JAX x64 disabled)
    const float* W1    = (const float*)d_in[3];
    const float* asrc1 = (const float*)d_in[4];
    const float* adst1 = (const float*)d_in[5];
    const float* b1    = (const float*)d_in[6];
    const float* W2    = (const float*)d_in[7];
    const float* asrc2 = (const float*)d_in[8];
    const float* adst2 = (const float*)d_in[9];
    const float* b2    = (const float*)d_in[10];
    const float* fcW   = (const float*)d_in[11];
    const float* fcb   = (const float*)d_in[12];
    float* out = (float*)d_out;

    float *t, *als, *ald;
    uint16_t *h1h, *h1l, *h2h, *h2l;
    uint16_t *w1h, *w1l, *w2h, *w2l, *wfh, *wfl;
    int *deg, *rowptr, *cursor, *srcs, *bsum, *boff;
    cudaGetSymbolAddress((void**)&t, g_t);
    cudaGetSymbolAddress((void**)&h1h, g_h1h);
    cudaGetSymbolAddress((void**)&h1l, g_h1l);
    cudaGetSymbolAddress((void**)&h2h, g_h2h);
    cudaGetSymbolAddress((void**)&h2l, g_h2l);
    cudaGetSymbolAddress((void**)&als, g_als);
    cudaGetSymbolAddress((void**)&ald, g_ald);
    cudaGetSymbolAddress((void**)&w1h, g_w1h);
    cudaGetSymbolAddress((void**)&w1l, g_w1l);
    cudaGetSymbolAddress((void**)&w2h, g_w2h);
    cudaGetSymbolAddress((void**)&w2l, g_w2l);
    cudaGetSymbolAddress((void**)&wfh, g_wfh);
    cudaGetSymbolAddress((void**)&wfl, g_wfl);
    cudaGetSymbolAddress((void**)&deg, g_deg);
    cudaGetSymbolAddress((void**)&rowptr, g_rowptr);
    cudaGetSymbolAddress((void**)&cursor, g_cursor);
    cudaGetSymbolAddress((void**)&srcs, g_srcs);
    cudaGetSymbolAddress((void**)&bsum, g_bsum);
    cudaGetSymbolAddress((void**)&boff, g_boff);

    // side stream + fork/join events, created once on the FIRST call
    // (the correctness call runs outside graph capture; capture reuses them)
    static cudaStream_t s2 = nullptr;
    static cudaEvent_t evFork = nullptr, evJoin = nullptr;
    if (s2 == nullptr) {
        cudaStreamCreateWithFlags(&s2, cudaStreamNonBlocking);
        cudaEventCreateWithFlags(&evFork, cudaEventDisableTiming);
        cudaEventCreateWithFlags(&evJoin, cudaEventDisableTiming);
    }

    const int NTILE = (NNODE + 127) / 128;   // 391
    dim3 gbig(NTILE, 2);
    dim3 gfc(NTILE, 1);

    // fork: side stream does CSR build + W2/fc splits, concurrent with GEMM1
    cudaEventRecord(evFork, 0);
    cudaStreamWaitEvent(s2, evFork, 0);

    cudaMemsetAsync(deg, 0, NNODE * sizeof(int), s2);
    k_count_deg<<<(NEDGE + 255) / 256, 256, 0, s2>>>(ei, deg);
    k_scan1<<<NBLK, 1024, 0, s2>>>(deg, rowptr, bsum);
    k_scan2<<<1, 32, 0, s2>>>(bsum, boff, rowptr);
    k_scan3<<<NBLK, 1024, 0, s2>>>(rowptr, cursor, boff);
    k_scatter<<<(EPAD + 255) / 256, 256, 0, s2>>>(ei, cursor, srcs);
    k_split_w<<<(FDIM * FDIM + 255) / 256, 256, 0, s2>>>(W2, w2h, w2l, FDIM, FDIM);
    k_split_w<<<(FDIM * OUTD + 255) / 256, 256, 0, s2>>>(fcW, wfh, wfl, FDIM, OUTD);
    cudaEventRecord(evJoin, s2);

    // main stream: W1 split + layer-1 GEMM (+fused logits)
    k_split_w<<<(FDIM * FDIM + 255) / 256, 256>>>(W1, w1h, w1l, FDIM, FDIM);
    k_gemm_mma<128, 256, false><<<gbig, 256>>>(x, nullptr, nullptr, w1h, w1l,
                                               nullptr, t, NNODE,
                                               asrc1, adst1, als, ald);

    // join: aggregation needs CSR (and layer-2 GEMM needs W2 split)
    cudaStreamWaitEvent(0, evJoin, 0);

    // layer 1 aggregate -> h1 (bf16 split)
    k_gat_aggregate<<<NNODE, 128>>>(t, rowptr, srcs, als, ald, b1, h1h, h1l);

    // layer 2
    k_gemm_mma<128, 256, true><<<gbig, 256>>>(nullptr, h1h, h1l, w2h, w2l,
                                              nullptr, t, NNODE,
                                              asrc2, adst2, als, ald);
    k_gat_aggregate<<<NNODE, 128>>>(t, rowptr, srcs, als, ald, b2, h2h, h2l);

    // fc head
    k_gemm_mma<64, 64, true><<<gfc, 256>>>(nullptr, h2h, h2l, wfh, wfl,
                                           fcb, out, NNODE,
                                           nullptr, nullptr, nullptr, nullptr);
}

// round 10
// speedup vs baseline: 2.8200x; 1.0322x over previous
#include <cuda_runtime.h>
#include <cuda_fp16.h>
#include <math.h>
#include <stdint.h>

#define NNODE 50000
#define NEDGE 800000
#define EPAD  (NEDGE + NNODE)
#define FDIM  256
#define NHEAD 4
#define OUTD  64
#define NBLK  ((NNODE + 1023) / 1024)   // 49 scan blocks

// ---------------- scratch ---------------------------------------------------
__device__ __align__(128) __half g_t[NNODE * FDIM];       // GEMM out, fp16 msgs
__device__ __align__(16) uint16_t g_h1h[NNODE * FDIM];    // layer-1 h, bf16 hi
__device__ __align__(16) uint16_t g_h1l[NNODE * FDIM];    // layer-1 h, bf16 lo
__device__ __align__(16) uint16_t g_h2h[NNODE * FDIM];
__device__ __align__(16) uint16_t g_h2l[NNODE * FDIM];
__device__ __align__(16) uint16_t g_w1h[FDIM * FDIM];     // W^T hi bf16 [N][K]
__device__ __align__(16) uint16_t g_w1l[FDIM * FDIM];
__device__ __align__(16) uint16_t g_w2h[FDIM * FDIM];
__device__ __align__(16) uint16_t g_w2l[FDIM * FDIM];
__device__ __align__(16) uint16_t g_wfh[OUTD * FDIM];
__device__ __align__(16) uint16_t g_wfl[OUTD * FDIM];
__device__ float g_als[NNODE * NHEAD];
__device__ float g_ald[NNODE * NHEAD];
__device__ int   g_deg[NNODE];
__device__ int   g_rowptr[NNODE + 1];
__device__ int   g_cursor[NNODE];
__device__ int   g_srcs[EPAD];
__device__ int   g_bsum[NBLK + 1];
__device__ int   g_boff[NBLK + 1];

__device__ __forceinline__ int clampi(int v, int lo, int hi) {
    return v < lo ? lo : (v > hi ? hi : v);
}
__device__ __forceinline__ uint32_t pack_bf16x2(float v0, float v1) {
    uint32_t d;
    asm("cvt.rn.bf16x2.f32 %0, %1, %2;" : "=r"(d) : "f"(v1), "f"(v0));
    return d;
}
__device__ __forceinline__ void mma_bf16(float* d, const uint32_t* a, const uint32_t* b) {
    asm volatile(
        "mma.sync.aligned.m16n8k16.row.col.f32.bf16.bf16.f32 "
        "{%0,%1,%2,%3}, {%4,%5,%6,%7}, {%8,%9}, {%0,%1,%2,%3};"
        : "+f"(d[0]), "+f"(d[1]), "+f"(d[2]), "+f"(d[3])
        : "r"(a[0]), "r"(a[1]), "r"(a[2]), "r"(a[3]), "r"(b[0]), "r"(b[1]));
}
#define LDSM_X4(r, addr)                                                     \
    asm volatile("ldmatrix.sync.aligned.m8n8.x4.shared.b16 {%0,%1,%2,%3}, [%4];" \
        : "=r"((r)[0]), "=r"((r)[1]), "=r"((r)[2]), "=r"((r)[3]) : "r"(addr))

// ---------------- CSR construction ------------------------------------------
__global__ void k_count_deg(const int* __restrict__ ei, int* deg) {
    int e = blockIdx.x * blockDim.x + threadIdx.x;
    if (e < NEDGE) atomicAdd(&deg[clampi(ei[NEDGE + e], 0, NNODE - 1)], 1);
}
// deg holds edge-only counts; +1 self loop folded into the scan
__global__ void k_scan1(const int* __restrict__ deg, int* rowptr, int* bsum) {
    int b = blockIdx.x, tid = threadIdx.x;
    int i = b * 1024 + tid;
    int v = (i < NNODE) ? (deg[i] + 1) : 0;
    int lane = tid & 31, w = tid >> 5;
    int x = v;
#pragma unroll
    for (int off = 1; off < 32; off <<= 1) {
        int y = __shfl_up_sync(0xffffffffu, x, off);
        if (lane >= off) x += y;
    }
    __shared__ int ws[32];
    if (lane == 31) ws[w] = x;
    __syncthreads();
    if (w == 0) {
        int s = ws[lane];
#pragma unroll
        for (int off = 1; off < 32; off <<= 1) {
            int y = __shfl_up_sync(0xffffffffu, s, off);
            if (lane >= off) s += y;
        }
        ws[lane] = s;
    }
    __syncthreads();
    int wo = (w > 0) ? ws[w - 1] : 0;
    int incl = x + wo;
    if (i < NNODE) rowptr[i] = incl - v;
    if (tid == 1023) bsum[b] = incl;
}
__global__ void k_scan2(const int* __restrict__ bsum, int* boff, int* rowptr) {
    if (threadIdx.x == 0) {
        int s = 0;
        for (int b = 0; b < NBLK; b++) { boff[b] = s; s += bsum[b]; }
        rowptr[NNODE] = s;
    }
}
__global__ void k_scan3(int* rowptr, int* cursor, const int* __restrict__ boff) {
    int i = blockIdx.x * blockDim.x + threadIdx.x;
    if (i < NNODE) {
        int r = rowptr[i] + boff[i >> 10];
        rowptr[i] = r;
        cursor[i] = r;
    }
}
__global__ void k_scatter(const int* __restrict__ ei, int* cursor, int* srcs) {
    int e = blockIdx.x * blockDim.x + threadIdx.x;
    if (e < NEDGE) {
        int s = clampi(ei[e], 0, NNODE - 1);
        int d = clampi(ei[NEDGE + e], 0, NNODE - 1);
        int pos = atomicAdd(&cursor[d], 1);
        if (pos >= 0 && pos < EPAD) srcs[pos] = s;
    } else if (e < EPAD) {
        int i = e - NEDGE;
        int pos = atomicAdd(&cursor[i], 1);
        if (pos >= 0 && pos < EPAD) srcs[pos] = i;
    }
}

// ---------------- weight split/transpose: W[K][N] -> hi/lo bf16 [N][K] ------
__global__ void k_split_w(const float* __restrict__ W, uint16_t* __restrict__ WH,
                          uint16_t* __restrict__ WL, int K, int N) {
    int i = blockIdx.x * blockDim.x + threadIdx.x;
    if (i < K * N) {
        int k = i / N, n = i % N;
        float v = W[i];
        uint32_t hw = pack_bf16x2(v, 0.f);
        float hf = __uint_as_float(hw << 16);
        uint32_t lw = pack_bf16x2(v - hf, 0.f);
        WH[n * K + k] = (uint16_t)(hw & 0xffffu);
        WL[n * K + k] = (uint16_t)(lw & 0xffffu);
    }
}

// ---------------- bf16-split tensor-core GEMM + fused logits ----------------
// HALF_C: C written as packed half2 (message table); else fp32 (+bias).
template<int BN, int NOUT, bool PRESPLIT, bool HALF_C>
__global__ void __launch_bounds__(256, 2)
k_gemm_mma(const float* __restrict__ A,
           const uint16_t* __restrict__ AH, const uint16_t* __restrict__ AL,
           const uint16_t* __restrict__ BH, const uint16_t* __restrict__ BL,
           const float* __restrict__ bias, void* __restrict__ C, int M,
           const float* __restrict__ a_src, const float* __restrict__ a_dst,
           float* __restrict__ als_out, float* __restrict__ ald_out) {
    constexpr int RS = 40;
    constexpr int WN = BN / 2;
    constexpr int NT = WN / 8;
    constexpr int NP = NT / 2;               // ldmatrix nt-pairs
    constexpr int A_F4 = 4;
    constexpr int A_U4 = 2;
    constexpr int B_U4 = BN * 4 / 256;

    __shared__ __align__(16) uint16_t sAh[128 * RS];
    __shared__ __align__(16) uint16_t sAl[128 * RS];
    __shared__ __align__(16) uint16_t sBh[BN * RS];
    __shared__ __align__(16) uint16_t sBl[BN * RS];

    const int tid  = threadIdx.x;
    const int wid  = tid >> 5, lane = tid & 31;
    const int wm   = wid & 3, wn = wid >> 2;
    const int g    = lane >> 2, tq = lane & 3;
    const int brow = blockIdx.x * 128;
    const int bcol = blockIdx.y * BN;

    float acc[2][NT][4];
#pragma unroll
    for (int mt = 0; mt < 2; mt++)
#pragma unroll
        for (int nt = 0; nt < NT; nt++)
#pragma unroll
            for (int r = 0; r < 4; r++) acc[mt][nt][r] = 0.f;

    const int lane8 = lane & 7, lh = (lane >> 3) & 1, lq = lane >> 4;
    const uint32_t sAh_b = (uint32_t)__cvta_generic_to_shared(sAh);
    const uint32_t sAl_b = (uint32_t)__cvta_generic_to_shared(sAl);
    const uint32_t sBh_b = (uint32_t)__cvta_generic_to_shared(sBh);
    const uint32_t sBl_b = (uint32_t)__cvta_generic_to_shared(sBl);
    uint32_t aHiA[2], aLoA[2], bHiA[NP], bLoA[NP];
#pragma unroll
    for (int mt = 0; mt < 2; mt++) {
        int ar = wm * 32 + mt * 16 + lane8 + lh * 8;
        int ac = lq * 8;
        aHiA[mt] = sAh_b + (ar * RS + ac) * 2;
        aLoA[mt] = sAl_b + (ar * RS + ac) * 2;
    }
#pragma unroll
    for (int p = 0; p < NP; p++) {
        int br = wn * WN + p * 16 + lane8 + lq * 8;
        int bc = lh * 8;
        bHiA[p] = sBh_b + (br * RS + bc) * 2;
        bLoA[p] = sBl_b + (br * RS + bc) * 2;
    }

    float4 aS[A_F4];
    uint4  aSh[A_U4], aSl[A_U4];
    uint4  bSh[B_U4], bSl[B_U4];

    auto load_regs = [&](int k0) {
        if (PRESPLIT) {
#pragma unroll
            for (int u = 0; u < A_U4; u++) {
                int q = tid + u * 256;
                int row = q >> 2, c8 = q & 3;
                int gr = brow + row;
                if (gr < M) {
                    size_t gi = (size_t)gr * 256 + k0 + c8 * 8;
                    aSh[u] = *reinterpret_cast<const uint4*>(&AH[gi]);
                    aSl[u] = *reinterpret_cast<const uint4*>(&AL[gi]);
                } else {
                    aSh[u] = make_uint4(0, 0, 0, 0);
                    aSl[u] = make_uint4(0, 0, 0, 0);
                }
            }
        } else {
#pragma unroll
            for (int u = 0; u < A_F4; u++) {
                int q = tid + u * 256;
                int row = q >> 3, f4 = q & 7;
                int gr = brow + row;
                aS[u] = make_float4(0.f, 0.f, 0.f, 0.f);
                if (gr < M) aS[u] = *reinterpret_cast<const float4*>(&A[(size_t)gr * 256 + k0 + f4 * 4]);
            }
        }
#pragma unroll
        for (int u = 0; u < B_U4; u++) {
            int q = tid + u * 256;
            int row = q >> 2, c8 = q & 3;
            size_t gi = (size_t)(bcol + row) * 256 + k0 + c8 * 8;
            bSh[u] = *reinterpret_cast<const uint4*>(&BH[gi]);
            bSl[u] = *reinterpret_cast<const uint4*>(&BL[gi]);
        }
    };
    auto split_store = [](uint16_t* hb, uint16_t* lb, int idx, float v0, float v1) {
        uint32_t hw = pack_bf16x2(v0, v1);
        float f0 = __uint_as_float(hw << 16);
        float f1 = __uint_as_float(hw & 0xffff0000u);
        uint32_t lw = pack_bf16x2(v0 - f0, v1 - f1);
        *reinterpret_cast<uint32_t*>(hb + idx) = hw;
        *reinterpret_cast<uint32_t*>(lb + idx) = lw;
    };
    auto store_smem = [&]() {
        if (PRESPLIT) {
#pragma unroll
            for (int u = 0; u < A_U4; u++) {
                int q = tid + u * 256;
                int row = q >> 2, c8 = q & 3;
                int idx = row * RS + c8 * 8;
                *reinterpret_cast<uint4*>(&sAh[idx]) = aSh[u];
                *reinterpret_cast<uint4*>(&sAl[idx]) = aSl[u];
            }
        } else {
#pragma unroll
            for (int u = 0; u < A_F4; u++) {
                int q = tid + u * 256;
                int row = q >> 3, f4 = q & 7;
                int idx = row * RS + f4 * 4;
                split_store(sAh, sAl, idx,     aS[u].x, aS[u].y);
                split_store(sAh, sAl, idx + 2, aS[u].z, aS[u].w);
            }
        }
#pragma unroll
        for (int u = 0; u < B_U4; u++) {
            int q = tid + u * 256;
            int row = q >> 2, c8 = q & 3;
            int idx = row * RS + c8 * 8;
            *reinterpret_cast<uint4*>(&sBh[idx]) = bSh[u];
            *reinterpret_cast<uint4*>(&sBl[idx]) = bSl[u];
        }
    };

    load_regs(0);
    store_smem();
    __syncthreads();

    for (int t = 0; t < 8; t++) {
        if (t + 1 < 8) load_regs((t + 1) * 32);

#pragma unroll
        for (int ks = 0; ks < 2; ks++) {
            const uint32_t kb = ks * 32;   // byte offset (16 halves)
            uint32_t ah[2][4], al[2][4];
            LDSM_X4(ah[0], aHiA[0] + kb);
            LDSM_X4(ah[1], aHiA[1] + kb);
            LDSM_X4(al[0], aLoA[0] + kb);
            LDSM_X4(al[1], aLoA[1] + kb);
#pragma unroll
            for (int p = 0; p < NP; p++) {
                uint32_t bh[4], bl[4];
                LDSM_X4(bh, bHiA[p] + kb);
                LDSM_X4(bl, bLoA[p] + kb);
#pragma unroll
                for (int mt = 0; mt < 2; mt++) {
                    mma_bf16(acc[mt][2 * p],     ah[mt], bh);
                    mma_bf16(acc[mt][2 * p],     ah[mt], bl);
                    mma_bf16(acc[mt][2 * p],     al[mt], bh);
                    mma_bf16(acc[mt][2 * p + 1], ah[mt], bh + 2);
                    mma_bf16(acc[mt][2 * p + 1], ah[mt], bl + 2);
                    mma_bf16(acc[mt][2 * p + 1], al[mt], bh + 2);
                }
            }
        }

        if (t + 1 < 8) {
            __syncthreads();
            store_smem();
            __syncthreads();
        }
    }

    // epilogue
#pragma unroll
    for (int mt = 0; mt < 2; mt++) {
        int r0 = brow + wm * 32 + mt * 16 + g;
        int r1 = r0 + 8;
#pragma unroll
        for (int nt = 0; nt < NT; nt++) {
            int col = bcol + wn * WN + nt * 8 + tq * 2;
            if (HALF_C) {
                __half2* Ch = reinterpret_cast<__half2*>(C);
                if (r0 < M)
                    Ch[(size_t)r0 * (NOUT / 2) + col / 2] =
                        __floats2half2_rn(acc[mt][nt][0], acc[mt][nt][1]);
                if (r1 < M)
                    Ch[(size_t)r1 * (NOUT / 2) + col / 2] =
                        __floats2half2_rn(acc[mt][nt][2], acc[mt][nt][3]);
            } else {
                float* Cf = reinterpret_cast<float*>(C);
                float b0 = 0.f, b1 = 0.f;
                if (bias) { b0 = bias[col]; b1 = bias[col + 1]; }
                if (r0 < M)
                    *reinterpret_cast<float2*>(&Cf[(size_t)r0 * NOUT + col]) =
                        make_float2(acc[mt][nt][0] + b0, acc[mt][nt][1] + b1);
                if (r1 < M)
                    *reinterpret_cast<float2*>(&Cf[(size_t)r1 * NOUT + col]) =
                        make_float2(acc[mt][nt][2] + b0, acc[mt][nt][3] + b1);
            }
        }
    }

    // fused attention logits (BN==128): head = blockIdx.y*2 + wn (fp32 acc)
    if (als_out) {
        int head = blockIdx.y * 2 + wn;
#pragma unroll
        for (int mt = 0; mt < 2; mt++) {
#pragma unroll
            for (int half = 0; half < 2; half++) {
                float ps = 0.f, pd = 0.f;
#pragma unroll
                for (int nt = 0; nt < NT; nt++) {
                    int col = bcol + wn * WN + nt * 8 + tq * 2;
                    float a0 = acc[mt][nt][half * 2 + 0];
                    float a1 = acc[mt][nt][half * 2 + 1];
                    ps += a0 * a_src[col] + a1 * a_src[col + 1];
                    pd += a0 * a_dst[col] + a1 * a_dst[col + 1];
                }
                ps += __shfl_xor_sync(0xffffffffu, ps, 1);
                pd += __shfl_xor_sync(0xffffffffu, pd, 1);
                ps += __shfl_xor_sync(0xffffffffu, ps, 2);
                pd += __shfl_xor_sync(0xffffffffu, pd, 2);
                int row = brow + wm * 32 + mt * 16 + g + half * 8;
                if (tq == 0 && row < M) {
                    als_out[row * NHEAD + head] = ps;
                    ald_out[row * NHEAD + head] = pd;
                }
            }
        }
    }
}

// ---------------- warp-synchronous aggregation (fp16 messages) --------------
// 128 threads/node; warp w owns head w (channels w*64..w*64+63 as 32 half2).
__global__ void __launch_bounds__(128)
k_gat_aggregate(const __half2* __restrict__ hsrc,
                const int* __restrict__ rowptr,
                const int* __restrict__ srcs,
                const float* __restrict__ als,
                const float* __restrict__ ald,
                const float* __restrict__ bias,
                uint16_t* __restrict__ outh, uint16_t* __restrict__ outl) {
    int n = blockIdx.x;
    int w = threadIdx.x >> 5;    // head == warp
    int lane = threadIdx.x & 31;

    int p0  = rowptr[n];
    int deg = rowptr[n + 1] - p0;

    float aldv = __ldg(&ald[n * NHEAD + w]);
    float accx = 0.f, accy = 0.f, dsum = 0.f;

    for (int base = 0; base < deg; base += 32) {
        int j = base + lane;
        int s = 0;
        float wt = 0.f;
        if (j < deg) {
            s = srcs[p0 + j];
            float e = als[s * NHEAD + w] + aldv;
            e = (e > 0.f) ? e : 0.2f * e;
            wt = __expf(e);
            dsum += wt;
        }
        int lim = min(32, deg - base);
#pragma unroll 4
        for (int j2 = 0; j2 < lim; j2++) {
            int   ss = __shfl_sync(0xffffffffu, s,  j2);
            float ww = __shfl_sync(0xffffffffu, wt, j2);
            float2 v = __half22float2(hsrc[(size_t)ss * 128 + w * 32 + lane]);
            accx += ww * v.x;
            accy += ww * v.y;
        }
    }

#pragma unroll
    for (int off = 16; off >= 1; off >>= 1)
        dsum += __shfl_xor_sync(0xffffffffu, dsum, off);

    float inv = 1.f / dsum;
    int c2 = w * 32 + lane;
    float o0 = accx * inv + bias[2 * c2];
    float o1 = accy * inv + bias[2 * c2 + 1];
    o0 = (o0 > 0.f) ? o0 : expm1f(o0);
    o1 = (o1 > 0.f) ? o1 : expm1f(o1);

    uint32_t hw = pack_bf16x2(o0, o1);
    float f0 = __uint_as_float(hw << 16);
    float f1 = __uint_as_float(hw & 0xffff0000u);
    uint32_t lw = pack_bf16x2(o0 - f0, o1 - f1);
    reinterpret_cast<uint32_t*>(outh)[(size_t)n * 128 + c2] = hw;
    reinterpret_cast<uint32_t*>(outl)[(size_t)n * 128 + c2] = lw;
}

// ---------------- launch ----------------------------------------------------
extern "C" void kernel_launch(void* const* d_in, const int* in_sizes, int n_in,
                              void* d_out, int out_size) {
    const float* x     = (const float*)d_in[0];
    const int*   ei    = (const int*)d_in[1];   // int32 (JAX x64 disabled)
    const float* W1    = (const float*)d_in[3];
    const float* asrc1 = (const float*)d_in[4];
    const float* adst1 = (const float*)d_in[5];
    const float* b1    = (const float*)d_in[6];
    const float* W2    = (const float*)d_in[7];
    const float* asrc2 = (const float*)d_in[8];
    const float* adst2 = (const float*)d_in[9];
    const float* b2    = (const float*)d_in[10];
    const float* fcW   = (const float*)d_in[11];
    const float* fcb   = (const float*)d_in[12];
    float* out = (float*)d_out;

    __half* t;
    float *als, *ald;
    uint16_t *h1h, *h1l, *h2h, *h2l;
    uint16_t *w1h, *w1l, *w2h, *w2l, *wfh, *wfl;
    int *deg, *rowptr, *cursor, *srcs, *bsum, *boff;
    cudaGetSymbolAddress((void**)&t, g_t);
    cudaGetSymbolAddress((void**)&h1h, g_h1h);
    cudaGetSymbolAddress((void**)&h1l, g_h1l);
    cudaGetSymbolAddress((void**)&h2h, g_h2h);
    cudaGetSymbolAddress((void**)&h2l, g_h2l);
    cudaGetSymbolAddress((void**)&als, g_als);
    cudaGetSymbolAddress((void**)&ald, g_ald);
    cudaGetSymbolAddress((void**)&w1h, g_w1h);
    cudaGetSymbolAddress((void**)&w1l, g_w1l);
    cudaGetSymbolAddress((void**)&w2h, g_w2h);
    cudaGetSymbolAddress((void**)&w2l, g_w2l);
    cudaGetSymbolAddress((void**)&wfh, g_wfh);
    cudaGetSymbolAddress((void**)&wfl, g_wfl);
    cudaGetSymbolAddress((void**)&deg, g_deg);
    cudaGetSymbolAddress((void**)&rowptr, g_rowptr);
    cudaGetSymbolAddress((void**)&cursor, g_cursor);
    cudaGetSymbolAddress((void**)&srcs, g_srcs);
    cudaGetSymbolAddress((void**)&bsum, g_bsum);
    cudaGetSymbolAddress((void**)&boff, g_boff);

    // side stream + fork/join events, created once on the FIRST call
    static cudaStream_t s2 = nullptr;
    static cudaEvent_t evFork = nullptr, evJoin = nullptr;
    if (s2 == nullptr) {
        cudaStreamCreateWithFlags(&s2, cudaStreamNonBlocking);
        cudaEventCreateWithFlags(&evFork, cudaEventDisableTiming);
        cudaEventCreateWithFlags(&evJoin, cudaEventDisableTiming);
    }

    const int NTILE = (NNODE + 127) / 128;   // 391
    dim3 gbig(NTILE, 2);
    dim3 gfc(NTILE, 1);

    // fork side stream
    cudaEventRecord(evFork, 0);
    cudaStreamWaitEvent(s2, evFork, 0);

    // kernel launch order chosen so GEMM1 is my 4th launch
    // (2 harness kernels precede; ncu -s 5 -c 1 profiles overall #6 = GEMM1)
    k_split_w<<<(FDIM * FDIM + 255) / 256, 256>>>(W1, w1h, w1l, FDIM, FDIM);   // #1
    cudaMemsetAsync(deg, 0, NNODE * sizeof(int), s2);
    k_count_deg<<<(NEDGE + 255) / 256, 256, 0, s2>>>(ei, deg);                  // #2
    k_scan1<<<NBLK, 1024, 0, s2>>>(deg, rowptr, bsum);                          // #3

    // #4: layer-1 GEMM (+fused logits), writes fp16 message table
    k_gemm_mma<128, 256, false, true><<<gbig, 256>>>(x, nullptr, nullptr,
                                                     w1h, w1l, nullptr, t, NNODE,
                                                     asrc1, adst1, als, ald);

    // rest of CSR + weight splits on side stream
    k_scan2<<<1, 32, 0, s2>>>(bsum, boff, rowptr);
    k_scan3<<<NBLK, 1024, 0, s2>>>(rowptr, cursor, boff);
    k_scatter<<<(EPAD + 255) / 256, 256, 0, s2>>>(ei, cursor, srcs);
    k_split_w<<<(FDIM * FDIM + 255) / 256, 256, 0, s2>>>(W2, w2h, w2l, FDIM, FDIM);
    k_split_w<<<(FDIM * OUTD + 255) / 256, 256, 0, s2>>>(fcW, wfh, wfl, FDIM, OUTD);
    cudaEventRecord(evJoin, s2);

    // join: aggregation needs CSR; layer-2 GEMM needs W2 split
    cudaStreamWaitEvent(0, evJoin, 0);

    // layer 1 aggregate -> h1 (bf16 split)
    k_gat_aggregate<<<NNODE, 128>>>((const __half2*)t, rowptr, srcs, als, ald,
                                    b1, h1h, h1l);

    // layer 2
    k_gemm_mma<128, 256, true, true><<<gbig, 256>>>(nullptr, h1h, h1l, w2h, w2l,
                                                    nullptr, t, NNODE,
                                                    asrc2, adst2, als, ald);
    k_gat_aggregate<<<NNODE, 128>>>((const __half2*)t, rowptr, srcs, als, ald,
                                    b2, h2h, h2l);

    // fc head (fp32 out + bias)
    k_gemm_mma<64, 64, true, false><<<gfc, 256>>>(nullptr, h2h, h2l, wfh, wfl,
                                                  fcb, out, NNODE,
                                                  nullptr, nullptr, nullptr, nullptr);
}